// round 2
// baseline (speedup 1.0000x reference)
#include <cuda_runtime.h>
#include <cuda_bf16.h>
#include <math.h>

// Problem constants
#define BSZ 4
#define SEQ 1024
#define DMODEL 512
#define NHEAD 8
#define DHEAD 64
#define NLAYER 4
#define ROWS (BSZ * SEQ)          // 4096
#define MAT (DMODEL * DMODEL)     // 262144

// ---------------- scratch (device globals; no allocation) ----------------
__device__ float g_z[ROWS * DMODEL];
__device__ float g_q[ROWS * DMODEL];
__device__ float g_k[ROWS * DMODEL];
__device__ float g_v[ROWS * DMODEL];
__device__ float g_r[ROWS * DMODEL];
__device__ float g_vb[ROWS * DMODEL];
__device__ float g_inner[ROWS * DMODEL];

// ---------------- LayerNorm ----------------
__inline__ __device__ float warp_sum(float v) {
#pragma unroll
    for (int o = 16; o; o >>= 1) v += __shfl_xor_sync(0xffffffffu, v, o);
    return v;
}

// one block per row, 128 threads, 4 floats each
__global__ void ln_kernel(const float* __restrict__ x,
                          const float* __restrict__ w,
                          const float* __restrict__ b,
                          float* __restrict__ y) {
    int row = blockIdx.x;
    int t = threadIdx.x;
    const float4 v = *(const float4*)&x[(size_t)row * DMODEL + t * 4];
    float s  = v.x + v.y + v.z + v.w;
    float sq = v.x * v.x + v.y * v.y + v.z * v.z + v.w * v.w;
    __shared__ float red[8];
    float s1 = warp_sum(s), s2 = warp_sum(sq);
    int warp = t >> 5, lane = t & 31;
    if (lane == 0) { red[warp] = s1; red[4 + warp] = s2; }
    __syncthreads();
    s1 = red[0] + red[1] + red[2] + red[3];
    s2 = red[4] + red[5] + red[6] + red[7];
    float mu = s1 * (1.0f / DMODEL);
    float var = s2 * (1.0f / DMODEL) - mu * mu;
    float inv = rsqrtf(var + 1e-5f);
    const float4 wv = *(const float4*)&w[t * 4];
    const float4 bv = *(const float4*)&b[t * 4];
    float4 o;
    o.x = (v.x - mu) * inv * wv.x + bv.x;
    o.y = (v.y - mu) * inv * wv.y + bv.y;
    o.z = (v.z - mu) * inv * wv.z + bv.z;
    o.w = (v.w - mu) * inv * wv.w + bv.w;
    *(float4*)&y[(size_t)row * DMODEL + t * 4] = o;
}

// ---------------- GEMM: C[M,N] = (A (* Amul?)) @ W^T (+ bias) (+ res) ----------------
// M=4096, N=512, K=512. BM=128, BN=64, BK=16, 256 threads, 8x4 micro-tile.
template <bool MUL, bool RES, bool BIAS>
__global__ __launch_bounds__(256)
void gemm_kernel(const float* __restrict__ A, const float* __restrict__ Amul,
                 const float* __restrict__ W, const float* __restrict__ bias,
                 const float* __restrict__ res, float* __restrict__ C) {
    __shared__ float As[16][132];  // [k][m], stride 132 (16B aligned, pad vs conflicts)
    __shared__ float Ws[16][68];   // [k][n]
    const int n0 = blockIdx.x * 64;
    const int m0 = blockIdx.y * 128;
    const int tid = threadIdx.x;
    const int tx = tid & 15;   // n: tx*4
    const int ty = tid >> 4;   // m: ty*8
    float acc[8][4];
#pragma unroll
    for (int i = 0; i < 8; i++)
#pragma unroll
        for (int j = 0; j < 4; j++) acc[i][j] = 0.0f;

    for (int k0 = 0; k0 < DMODEL; k0 += 16) {
        // load A tile: 128x16 = 2048 floats, 2 float4 per thread
#pragma unroll
        for (int it = 0; it < 2; it++) {
            int li = tid + it * 256;
            int m = li >> 2;
            int kq = (li & 3) * 4;
            float4 a = *(const float4*)&A[(size_t)(m0 + m) * DMODEL + k0 + kq];
            if (MUL) {
                float4 u = *(const float4*)&Amul[(size_t)(m0 + m) * DMODEL + k0 + kq];
                a.x *= u.x; a.y *= u.y; a.z *= u.z; a.w *= u.w;
            }
            As[kq + 0][m] = a.x;
            As[kq + 1][m] = a.y;
            As[kq + 2][m] = a.z;
            As[kq + 3][m] = a.w;
        }
        // load W tile: 64x16 = 1024 floats, 1 float4 per thread
        {
            int n = tid >> 2;
            int kq = (tid & 3) * 4;
            float4 wv = *(const float4*)&W[(size_t)(n0 + n) * DMODEL + k0 + kq];
            Ws[kq + 0][n] = wv.x;
            Ws[kq + 1][n] = wv.y;
            Ws[kq + 2][n] = wv.z;
            Ws[kq + 3][n] = wv.w;
        }
        __syncthreads();
#pragma unroll
        for (int kk = 0; kk < 16; kk++) {
            float4 a0 = *(const float4*)&As[kk][ty * 8];
            float4 a1 = *(const float4*)&As[kk][ty * 8 + 4];
            float4 b4 = *(const float4*)&Ws[kk][tx * 4];
            float av[8] = {a0.x, a0.y, a0.z, a0.w, a1.x, a1.y, a1.z, a1.w};
            float bv[4] = {b4.x, b4.y, b4.z, b4.w};
#pragma unroll
            for (int i = 0; i < 8; i++)
#pragma unroll
                for (int j = 0; j < 4; j++) acc[i][j] += av[i] * bv[j];
        }
        __syncthreads();
    }

    float4 bias4 = make_float4(0.f, 0.f, 0.f, 0.f);
    if (BIAS) bias4 = *(const float4*)&bias[n0 + tx * 4];
#pragma unroll
    for (int i = 0; i < 8; i++) {
        size_t off = (size_t)(m0 + ty * 8 + i) * DMODEL + n0 + tx * 4;
        float4 o;
        o.x = acc[i][0]; o.y = acc[i][1]; o.z = acc[i][2]; o.w = acc[i][3];
        if (BIAS) { o.x += bias4.x; o.y += bias4.y; o.z += bias4.z; o.w += bias4.w; }
        if (RES) {
            float4 rr = *(const float4*)&res[off];
            o.x += rr.x; o.y += rr.y; o.z += rr.z; o.w += rr.w;
        }
        *(float4*)&C[off] = o;
    }
}

// ---------------- Flash attention ----------------
// block = (q-tile of 64, head, batch); 256 threads; online softmax.
// smem: Qt[d][r], Kt[d][c], Vs[c][d], Pt[c][r], each 64x68 floats.
#define AST 68
#define ATT_SMEM_BYTES (4 * 64 * AST * 4)

__global__ __launch_bounds__(256)
void attn_kernel(const float* __restrict__ q, const float* __restrict__ k,
                 const float* __restrict__ v, const int* __restrict__ mask,
                 float* __restrict__ vbar) {
    extern __shared__ float sm[];
    float* Qt = sm;
    float* Kt = sm + 64 * AST;
    float* Vs = sm + 2 * 64 * AST;
    float* Pt = sm + 3 * 64 * AST;
    const int b = blockIdx.z, h = blockIdx.y, q0 = blockIdx.x * 64;
    const int tid = threadIdx.x;
    const int tx = tid & 15, ty = tid >> 4;
    const float scale = 0.125f;  // 1/sqrt(64)

    // load Q tile (transposed), pre-scaled. 64 rows x 64 d:
    // 4 threads per row, each loads 4 float4 (16 floats).
    {
        int rr = tid >> 2;
        int c0 = (tid & 3) * 16;
        size_t base = ((size_t)(b * SEQ + q0 + rr) * DMODEL) + h * DHEAD;
#pragma unroll
        for (int ii = 0; ii < 4; ii++) {
            int dq = c0 + ii * 4;
            float4 qv = *(const float4*)&q[base + dq];
            Qt[(dq + 0) * AST + rr] = qv.x * scale;
            Qt[(dq + 1) * AST + rr] = qv.y * scale;
            Qt[(dq + 2) * AST + rr] = qv.z * scale;
            Qt[(dq + 3) * AST + rr] = qv.w * scale;
        }
    }

    float o[4][4];
#pragma unroll
    for (int i = 0; i < 4; i++)
#pragma unroll
        for (int j = 0; j < 4; j++) o[i][j] = 0.0f;
    float m_i[4], l_i[4];
#pragma unroll
    for (int i = 0; i < 4; i++) { m_i[i] = -1e30f; l_i[i] = 0.0f; }

    for (int jt = 0; jt < SEQ / 64; jt++) {
        // load K (transposed) and V tiles: full 64x64 each
        {
            int cc = tid >> 2;
            int c0 = (tid & 3) * 16;
            size_t base = ((size_t)(b * SEQ + jt * 64 + cc) * DMODEL) + h * DHEAD;
#pragma unroll
            for (int ii = 0; ii < 4; ii++) {
                int dq = c0 + ii * 4;
                float4 kv = *(const float4*)&k[base + dq];
                Kt[(dq + 0) * AST + cc] = kv.x;
                Kt[(dq + 1) * AST + cc] = kv.y;
                Kt[(dq + 2) * AST + cc] = kv.z;
                Kt[(dq + 3) * AST + cc] = kv.w;
                float4 vv = *(const float4*)&v[base + dq];
                *(float4*)&Vs[cc * AST + dq] = vv;
            }
        }
        __syncthreads();

        float sacc[4][4];
#pragma unroll
        for (int i = 0; i < 4; i++)
#pragma unroll
            for (int j = 0; j < 4; j++) sacc[i][j] = 0.0f;
#pragma unroll 16
        for (int kk = 0; kk < 64; kk++) {
            float4 a = *(const float4*)&Qt[kk * AST + ty * 4];
            float4 bb = *(const float4*)&Kt[kk * AST + tx * 4];
            float av[4] = {a.x, a.y, a.z, a.w};
            float bv[4] = {bb.x, bb.y, bb.z, bb.w};
#pragma unroll
            for (int i = 0; i < 4; i++)
#pragma unroll
                for (int j = 0; j < 4; j++) sacc[i][j] += av[i] * bv[j];
        }
        // mask (src_mask is [B,1,1,S])
#pragma unroll
        for (int j = 0; j < 4; j++) {
            int mv = mask[b * SEQ + jt * 64 + tx * 4 + j];
            if (mv == 0) {
#pragma unroll
                for (int i = 0; i < 4; i++) sacc[i][j] = -1e10f;
            }
        }
        // online softmax per row (16 tx-lanes per row live in one half-warp)
#pragma unroll
        for (int i = 0; i < 4; i++) {
            float rmax = fmaxf(fmaxf(sacc[i][0], sacc[i][1]), fmaxf(sacc[i][2], sacc[i][3]));
#pragma unroll
            for (int off = 8; off; off >>= 1)
                rmax = fmaxf(rmax, __shfl_xor_sync(0xffffffffu, rmax, off));
            float mn = fmaxf(m_i[i], rmax);
            float corr = __expf(m_i[i] - mn);
            m_i[i] = mn;
            float rsum = 0.0f;
#pragma unroll
            for (int j = 0; j < 4; j++) {
                float p = __expf(sacc[i][j] - mn);
                sacc[i][j] = p;
                rsum += p;
            }
#pragma unroll
            for (int off = 8; off; off >>= 1)
                rsum += __shfl_xor_sync(0xffffffffu, rsum, off);
            l_i[i] = l_i[i] * corr + rsum;
#pragma unroll
            for (int j = 0; j < 4; j++) o[i][j] *= corr;
        }
        // store P transposed: Pt[c][r]
#pragma unroll
        for (int j = 0; j < 4; j++)
#pragma unroll
            for (int i = 0; i < 4; i++)
                Pt[(tx * 4 + j) * AST + ty * 4 + i] = sacc[i][j];
        __syncthreads();
#pragma unroll 16
        for (int kk = 0; kk < 64; kk++) {
            float4 a = *(const float4*)&Pt[kk * AST + ty * 4];
            float4 bb = *(const float4*)&Vs[kk * AST + tx * 4];
            float av[4] = {a.x, a.y, a.z, a.w};
            float bv[4] = {bb.x, bb.y, bb.z, bb.w};
#pragma unroll
            for (int i = 0; i < 4; i++)
#pragma unroll
                for (int j = 0; j < 4; j++) o[i][j] += av[i] * bv[j];
        }
        __syncthreads();
    }
    // write v_bar in [b, s, h*64+d] layout
#pragma unroll
    for (int i = 0; i < 4; i++) {
        float rl = 1.0f / l_i[i];
        float4 ov;
        ov.x = o[i][0] * rl; ov.y = o[i][1] * rl; ov.z = o[i][2] * rl; ov.w = o[i][3] * rl;
        *(float4*)&vbar[((size_t)(b * SEQ + q0 + ty * 4 + i) * DMODEL) + h * DHEAD + tx * 4] = ov;
    }
}

// ---------------- KAN inner: x=tanh(z), B-spline basis (order 3, first 2 fns) ----------------
__device__ __forceinline__ float2 bspline01(float x) {
    const float h = 2.0f / 7.0f;
    const float i1 = 3.5f;            // 1/h
    const float i2 = 1.75f;           // 1/(2h)
    const float i3 = 7.0f / 6.0f;     // 1/(3h)
    float B0[5];
#pragma unroll
    for (int kk = 0; kk < 5; kk++) {
        float tk = -1.0f + kk * h;
        B0[kk] = (x >= tk && x < tk + h) ? 1.0f : 0.0f;
    }
    float B1[4];
#pragma unroll
    for (int kk = 0; kk < 4; kk++) {
        float tk = -1.0f + kk * h;
        B1[kk] = (x - tk) * i1 * B0[kk] + ((tk + 2.0f * h) - x) * i1 * B0[kk + 1];
    }
    float B2[3];
#pragma unroll
    for (int kk = 0; kk < 3; kk++) {
        float tk = -1.0f + kk * h;
        B2[kk] = (x - tk) * i2 * B1[kk] + ((tk + 3.0f * h) - x) * i2 * B1[kk + 1];
    }
    float2 r;
    {
        float tk = -1.0f;
        r.x = (x - tk) * i3 * B2[0] + ((tk + 4.0f * h) - x) * i3 * B2[1];
        tk = -1.0f + h;
        r.y = (x - tk) * i3 * B2[1] + ((tk + 4.0f * h) - x) * i3 * B2[2];
    }
    return r;
}

__global__ void kan_inner_kernel(const float* __restrict__ z,
                                 const float* __restrict__ ic,  // [D,5] for this layer
                                 float* __restrict__ inner) {
    int idx = blockIdx.x * blockDim.x + threadIdx.x;
    int d = idx & (DMODEL - 1);
    float x = tanhf(z[idx]);
    float2 bs = bspline01(x);
    inner[idx] = bs.x * ic[d * 5 + 0] + bs.y * ic[d * 5 + 1];
}

// ---------------- host ----------------
extern "C" void kernel_launch(void* const* d_in, const int* in_sizes, int n_in,
                              void* d_out, int out_size) {
    const float* src    = (const float*)d_in[0];
    const float* ln1_w  = (const float*)d_in[1];
    const float* ln1_b  = (const float*)d_in[2];
    const float* ln2_w  = (const float*)d_in[3];
    const float* ln2_b  = (const float*)d_in[4];
    const float* ln3_w  = (const float*)d_in[5];
    const float* ln3_b  = (const float*)d_in[6];
    const float* Wq_w   = (const float*)d_in[7];
    const float* Wq_b   = (const float*)d_in[8];
    const float* Wk_w   = (const float*)d_in[9];
    const float* Wk_b   = (const float*)d_in[10];
    const float* Wv_w   = (const float*)d_in[11];
    const float* Wv_b   = (const float*)d_in[12];
    const float* Wr_w   = (const float*)d_in[13];
    const float* Wr_b   = (const float*)d_in[14];
    const float* Wo_w   = (const float*)d_in[15];
    const float* Wo_b   = (const float*)d_in[16];
    const float* inner_c= (const float*)d_in[17];
    const float* outer_c= (const float*)d_in[18];
    const int*   mask   = (const int*)d_in[19];
    float* out = (float*)d_out;

    float *z, *q, *k, *v, *r, *vb, *inner;
    cudaGetSymbolAddress((void**)&z, g_z);
    cudaGetSymbolAddress((void**)&q, g_q);
    cudaGetSymbolAddress((void**)&k, g_k);
    cudaGetSymbolAddress((void**)&v, g_v);
    cudaGetSymbolAddress((void**)&r, g_r);
    cudaGetSymbolAddress((void**)&vb, g_vb);
    cudaGetSymbolAddress((void**)&inner, g_inner);

    cudaFuncSetAttribute(attn_kernel, cudaFuncAttributeMaxDynamicSharedMemorySize,
                         ATT_SMEM_BYTES);

    cudaMemcpyAsync(out, src, (size_t)ROWS * DMODEL * sizeof(float),
                    cudaMemcpyDeviceToDevice, 0);

    dim3 ggrid(DMODEL / 64, ROWS / 128);
    for (int l = 0; l < NLAYER; l++) {
        const float* l1w = ln1_w + l * DMODEL;
        const float* l1b = ln1_b + l * DMODEL;
        // --- attention block ---
        ln_kernel<<<ROWS, 128>>>(out, l1w, l1b, z);
        gemm_kernel<false, false, true><<<ggrid, 256>>>(z, nullptr, Wq_w + l * MAT, Wq_b + l * DMODEL, nullptr, q);
        gemm_kernel<false, false, true><<<ggrid, 256>>>(z, nullptr, Wk_w + l * MAT, Wk_b + l * DMODEL, nullptr, k);
        gemm_kernel<false, false, true><<<ggrid, 256>>>(z, nullptr, Wv_w + l * MAT, Wv_b + l * DMODEL, nullptr, v);
        gemm_kernel<false, false, true><<<ggrid, 256>>>(z, nullptr, Wr_w + l * MAT, Wr_b + l * DMODEL, nullptr, r);
        attn_kernel<<<dim3(SEQ / 64, NHEAD, BSZ), 256, ATT_SMEM_BYTES>>>(q, k, v, mask, vb);
        // src = src + (vbar * R) @ Wo^T + Wo_b
        gemm_kernel<true, true, true><<<ggrid, 256>>>(vb, r, Wo_w + l * MAT, Wo_b + l * DMODEL, out, out);
        // --- KAN block ---
        ln_kernel<<<ROWS, 128>>>(out, ln2_w + l * DMODEL, ln2_b + l * DMODEL, z);
        kan_inner_kernel<<<ROWS * DMODEL / 256, 256>>>(z, inner_c + l * DMODEL * 5, inner);
        // src = src + inner @ outer_c^T
        gemm_kernel<false, true, false><<<ggrid, 256>>>(inner, nullptr, outer_c + l * MAT, nullptr, out, out);
        // src = LN3(src) in-place
        ln_kernel<<<ROWS, 128>>>(out, ln3_w + l * DMODEL, ln3_b + l * DMODEL, out);
    }
}

// round 5
// speedup vs baseline: 1.3087x; 1.3087x over previous
#include <cuda_runtime.h>
#include <cuda_bf16.h>
#include <math.h>
#include <stdint.h>

// Problem constants
#define BSZ 4
#define SEQ 1024
#define DMODEL 512
#define NHEAD 8
#define DHEAD 64
#define NLAYER 4
#define ROWS (BSZ * SEQ)          // 4096
#define MAT (DMODEL * DMODEL)     // 262144

// ---------------- scratch (device globals; no allocation) ----------------
__device__ float g_z[ROWS * DMODEL];
__device__ float g_q[ROWS * DMODEL];
__device__ float g_k[ROWS * DMODEL];
__device__ float g_v[ROWS * DMODEL];
__device__ float g_r[ROWS * DMODEL];
__device__ float g_vb[ROWS * DMODEL];
__device__ float g_inner[ROWS * DMODEL];
// bf16 split buffers
__device__ __nv_bfloat16 g_wh[24 * MAT];   // weights hi: [type0..5][layer0..3][MAT]
__device__ __nv_bfloat16 g_wl[24 * MAT];   // weights lo
__device__ __nv_bfloat16 g_ah[ROWS * DMODEL];  // activation hi
__device__ __nv_bfloat16 g_al[ROWS * DMODEL];  // activation lo

// ---------------- PTX helpers (sm_80+ features only; no 'a'-suffix arch) ----
__device__ __forceinline__ uint32_t smem_to_u32(const void* p) {
    uint32_t a;
    asm("{ .reg .u64 t; cvta.to.shared.u64 t, %1; cvt.u32.u64 %0, t; }" : "=r"(a) : "l"(p));
    return a;
}
__device__ __forceinline__ void cp_async16(uint32_t dst, const void* src) {
    asm volatile("cp.async.cg.shared.global [%0], [%1], 16;" :: "r"(dst), "l"(src));
}
__device__ __forceinline__ void ldsm4(uint32_t& r0, uint32_t& r1, uint32_t& r2, uint32_t& r3,
                                      uint32_t a) {
    asm volatile("ldmatrix.sync.aligned.m8n8.x4.shared.b16 {%0,%1,%2,%3}, [%4];"
                 : "=r"(r0), "=r"(r1), "=r"(r2), "=r"(r3) : "r"(a));
}
__device__ __forceinline__ void mma16816(float* c, uint32_t a0, uint32_t a1, uint32_t a2,
                                         uint32_t a3, uint32_t b0, uint32_t b1) {
    asm volatile(
        "mma.sync.aligned.m16n8k16.row.col.f32.bf16.bf16.f32 "
        "{%0,%1,%2,%3}, {%4,%5,%6,%7}, {%8,%9}, {%0,%1,%2,%3};"
        : "+f"(c[0]), "+f"(c[1]), "+f"(c[2]), "+f"(c[3])
        : "r"(a0), "r"(a1), "r"(a2), "r"(a3), "r"(b0), "r"(b1));
}

// ---------------- LayerNorm ----------------
__inline__ __device__ float warp_sum(float v) {
#pragma unroll
    for (int o = 16; o; o >>= 1) v += __shfl_xor_sync(0xffffffffu, v, o);
    return v;
}

__global__ void ln_kernel(const float* __restrict__ x,
                          const float* __restrict__ w,
                          const float* __restrict__ b,
                          float* __restrict__ y) {
    int row = blockIdx.x;
    int t = threadIdx.x;
    const float4 v = *(const float4*)&x[(size_t)row * DMODEL + t * 4];
    float s  = v.x + v.y + v.z + v.w;
    float sq = v.x * v.x + v.y * v.y + v.z * v.z + v.w * v.w;
    __shared__ float red[8];
    float s1 = warp_sum(s), s2 = warp_sum(sq);
    int warp = t >> 5, lane = t & 31;
    if (lane == 0) { red[warp] = s1; red[4 + warp] = s2; }
    __syncthreads();
    s1 = red[0] + red[1] + red[2] + red[3];
    s2 = red[4] + red[5] + red[6] + red[7];
    float mu = s1 * (1.0f / DMODEL);
    float var = s2 * (1.0f / DMODEL) - mu * mu;
    float inv = rsqrtf(var + 1e-5f);
    const float4 wv = *(const float4*)&w[t * 4];
    const float4 bv = *(const float4*)&b[t * 4];
    float4 o;
    o.x = (v.x - mu) * inv * wv.x + bv.x;
    o.y = (v.y - mu) * inv * wv.y + bv.y;
    o.z = (v.z - mu) * inv * wv.z + bv.z;
    o.w = (v.w - mu) * inv * wv.w + bv.w;
    *(float4*)&y[(size_t)row * DMODEL + t * 4] = o;
}

// ---------------- fp32 -> bf16 hi/lo split ----------------
__device__ __forceinline__ void split_store(float v, __nv_bfloat16* hi, __nv_bfloat16* lo) {
    __nv_bfloat16 h = __float2bfloat16(v);
    *hi = h;
    *lo = __float2bfloat16(v - __bfloat162float(h));
}

__global__ void split_kernel(const float* __restrict__ x,
                             __nv_bfloat16* __restrict__ hi,
                             __nv_bfloat16* __restrict__ lo, int n4) {
    int i = blockIdx.x * blockDim.x + threadIdx.x;
    if (i >= n4) return;
    float4 v = ((const float4*)x)[i];
    __nv_bfloat16 hv[4], lv[4];
    split_store(v.x, &hv[0], &lv[0]);
    split_store(v.y, &hv[1], &lv[1]);
    split_store(v.z, &hv[2], &lv[2]);
    split_store(v.w, &hv[3], &lv[3]);
    ((uint64_t*)hi)[i] = *(uint64_t*)hv;
    ((uint64_t*)lo)[i] = *(uint64_t*)lv;
}

__global__ void mul_split_kernel(const float* __restrict__ a, const float* __restrict__ b,
                                 __nv_bfloat16* __restrict__ hi,
                                 __nv_bfloat16* __restrict__ lo, int n4) {
    int i = blockIdx.x * blockDim.x + threadIdx.x;
    if (i >= n4) return;
    float4 va = ((const float4*)a)[i];
    float4 vb = ((const float4*)b)[i];
    __nv_bfloat16 hv[4], lv[4];
    split_store(va.x * vb.x, &hv[0], &lv[0]);
    split_store(va.y * vb.y, &hv[1], &lv[1]);
    split_store(va.z * vb.z, &hv[2], &lv[2]);
    split_store(va.w * vb.w, &hv[3], &lv[3]);
    ((uint64_t*)hi)[i] = *(uint64_t*)hv;
    ((uint64_t*)lo)[i] = *(uint64_t*)lv;
}

// ---------------- mma.sync bf16 GEMM (3-split) ----------------
// C[M=4096, N=512] = A @ W^T (+bias)(+res). CTA tile 128x128, BK=64.
// 8 warps, warp tile 64x32. K: 3 splits x 8 chunks of 64 = 24 chunks.
// smem per stage: A 128x64 bf16 (16KB) + B 128x64 bf16 (16KB); 2 stages = 64KB.
#define GEMM_SMEM 65536
#define NCHUNK 24

template <bool BIAS, bool RES>
__global__ __launch_bounds__(256, 1)
void mma_gemm(const __nv_bfloat16* __restrict__ ah, const __nv_bfloat16* __restrict__ al,
              const __nv_bfloat16* __restrict__ wh, const __nv_bfloat16* __restrict__ wl,
              const float* __restrict__ bias, const float* __restrict__ res,
              float* __restrict__ C) {
    extern __shared__ char smem[];
    const uint32_t smb = smem_to_u32(smem);
    const int tid = threadIdx.x;
    const int wid = tid >> 5, lane = tid & 31;
    const int n0 = blockIdx.x * 128, m0 = blockIdx.y * 128;
    const int wm = (wid >> 2) * 64;
    const int wn = (wid & 3) * 32;

    float acc[4][4][4];
#pragma unroll
    for (int i = 0; i < 4; i++)
#pragma unroll
        for (int j = 0; j < 4; j++)
#pragma unroll
            for (int q = 0; q < 4; q++) acc[i][j][q] = 0.0f;

    // stage chunk c into stage s (xor-swizzled 128B rows)
    auto stage = [&](int c, int s) {
        int sp = c >> 3, kc = (c & 7) * 64;
        const __nv_bfloat16* asrc = (sp == 2) ? al : ah;
        const __nv_bfloat16* wsrc = (sp == 1) ? wl : wh;
        int row = tid >> 1;
        int g0 = (tid & 1) * 4;
        const char* ga = (const char*)(asrc + (size_t)(m0 + row) * DMODEL + kc);
        const char* gw = (const char*)(wsrc + (size_t)(n0 + row) * DMODEL + kc);
        uint32_t sa = smb + s * 32768 + row * 128;
        uint32_t sb = sa + 16384;
#pragma unroll
        for (int j = 0; j < 4; j++) {
            int g = g0 + j;
            uint32_t so = (uint32_t)((g ^ (row & 7)) << 4);
            cp_async16(sa + so, ga + g * 16);
            cp_async16(sb + so, gw + g * 16);
        }
    };

    auto compute = [&](int s) {
        uint32_t Abase = smb + s * 32768;
        uint32_t Bbase = Abase + 16384;
#pragma unroll
        for (int k16 = 0; k16 < 4; k16++) {
            uint32_t a[4][4];
#pragma unroll
            for (int mi = 0; mi < 4; mi++) {
                int row = wm + mi * 16 + (lane & 15);
                int g = k16 * 2 + (lane >> 4);
                uint32_t addr = Abase + row * 128 + ((g ^ (row & 7)) << 4);
                ldsm4(a[mi][0], a[mi][1], a[mi][2], a[mi][3], addr);
            }
            uint32_t b[2][4];
#pragma unroll
            for (int nj = 0; nj < 2; nj++) {
                int row = wn + nj * 16 + ((lane >> 4) << 3) + (lane & 7);
                int g = k16 * 2 + ((lane >> 3) & 1);
                uint32_t addr = Bbase + row * 128 + ((g ^ (row & 7)) << 4);
                ldsm4(b[nj][0], b[nj][1], b[nj][2], b[nj][3], addr);
            }
#pragma unroll
            for (int mi = 0; mi < 4; mi++)
#pragma unroll
                for (int ni = 0; ni < 4; ni++)
                    mma16816(acc[mi][ni], a[mi][0], a[mi][1], a[mi][2], a[mi][3],
                             b[ni >> 1][(ni & 1) * 2], b[ni >> 1][(ni & 1) * 2 + 1]);
        }
    };

    stage(0, 0);
    asm volatile("cp.async.commit_group;");
    stage(1, 1);
    asm volatile("cp.async.commit_group;");

    for (int c = 0; c < NCHUNK; c++) {
        if (c < NCHUNK - 1) asm volatile("cp.async.wait_group 1;");
        else                asm volatile("cp.async.wait_group 0;");
        __syncthreads();
        compute(c & 1);
        __syncthreads();
        if (c + 2 < NCHUNK) {
            stage(c + 2, c & 1);
            asm volatile("cp.async.commit_group;");
        }
    }

    // epilogue
    const int lr = lane >> 2;
    const int lc = (lane & 3) * 2;
#pragma unroll
    for (int mi = 0; mi < 4; mi++) {
#pragma unroll
        for (int ni = 0; ni < 4; ni++) {
            int col = n0 + wn + ni * 8 + lc;
            float bx = 0.0f, by = 0.0f;
            if (BIAS) { bx = bias[col]; by = bias[col + 1]; }
            int row0 = m0 + wm + mi * 16 + lr;
            float2 v0, v1;
            v0.x = acc[mi][ni][0] + bx; v0.y = acc[mi][ni][1] + by;
            v1.x = acc[mi][ni][2] + bx; v1.y = acc[mi][ni][3] + by;
            size_t o0 = (size_t)row0 * DMODEL + col;
            size_t o1 = (size_t)(row0 + 8) * DMODEL + col;
            if (RES) {
                float2 r0 = *(const float2*)&res[o0];
                float2 r1 = *(const float2*)&res[o1];
                v0.x += r0.x; v0.y += r0.y;
                v1.x += r1.x; v1.y += r1.y;
            }
            *(float2*)&C[o0] = v0;
            *(float2*)&C[o1] = v1;
        }
    }
}

// ---------------- Flash attention (fp32 SIMT) ----------------
#define AST 68
#define ATT_SMEM_BYTES (4 * 64 * AST * 4)

__global__ __launch_bounds__(256)
void attn_kernel(const float* __restrict__ q, const float* __restrict__ k,
                 const float* __restrict__ v, const int* __restrict__ mask,
                 float* __restrict__ vbar) {
    extern __shared__ float sm[];
    float* Qt = sm;
    float* Kt = sm + 64 * AST;
    float* Vs = sm + 2 * 64 * AST;
    float* Pt = sm + 3 * 64 * AST;
    const int b = blockIdx.z, h = blockIdx.y, q0 = blockIdx.x * 64;
    const int tid = threadIdx.x;
    const int tx = tid & 15, ty = tid >> 4;
    const float scale = 0.125f;

    {
        int rr = tid >> 2;
        int c0 = (tid & 3) * 16;
        size_t base = ((size_t)(b * SEQ + q0 + rr) * DMODEL) + h * DHEAD;
#pragma unroll
        for (int ii = 0; ii < 4; ii++) {
            int dq = c0 + ii * 4;
            float4 qv = *(const float4*)&q[base + dq];
            Qt[(dq + 0) * AST + rr] = qv.x * scale;
            Qt[(dq + 1) * AST + rr] = qv.y * scale;
            Qt[(dq + 2) * AST + rr] = qv.z * scale;
            Qt[(dq + 3) * AST + rr] = qv.w * scale;
        }
    }

    float o[4][4];
#pragma unroll
    for (int i = 0; i < 4; i++)
#pragma unroll
        for (int j = 0; j < 4; j++) o[i][j] = 0.0f;
    float m_i[4], l_i[4];
#pragma unroll
    for (int i = 0; i < 4; i++) { m_i[i] = -1e30f; l_i[i] = 0.0f; }

    for (int jt = 0; jt < SEQ / 64; jt++) {
        {
            int cc = tid >> 2;
            int c0 = (tid & 3) * 16;
            size_t base = ((size_t)(b * SEQ + jt * 64 + cc) * DMODEL) + h * DHEAD;
#pragma unroll
            for (int ii = 0; ii < 4; ii++) {
                int dq = c0 + ii * 4;
                float4 kv = *(const float4*)&k[base + dq];
                Kt[(dq + 0) * AST + cc] = kv.x;
                Kt[(dq + 1) * AST + cc] = kv.y;
                Kt[(dq + 2) * AST + cc] = kv.z;
                Kt[(dq + 3) * AST + cc] = kv.w;
                float4 vv = *(const float4*)&v[base + dq];
                *(float4*)&Vs[cc * AST + dq] = vv;
            }
        }
        __syncthreads();

        float sacc[4][4];
#pragma unroll
        for (int i = 0; i < 4; i++)
#pragma unroll
            for (int j = 0; j < 4; j++) sacc[i][j] = 0.0f;
#pragma unroll 16
        for (int kk = 0; kk < 64; kk++) {
            float4 a = *(const float4*)&Qt[kk * AST + ty * 4];
            float4 bb = *(const float4*)&Kt[kk * AST + tx * 4];
            float av[4] = {a.x, a.y, a.z, a.w};
            float bv[4] = {bb.x, bb.y, bb.z, bb.w};
#pragma unroll
            for (int i = 0; i < 4; i++)
#pragma unroll
                for (int j = 0; j < 4; j++) sacc[i][j] += av[i] * bv[j];
        }
#pragma unroll
        for (int j = 0; j < 4; j++) {
            int mv = mask[b * SEQ + jt * 64 + tx * 4 + j];
            if (mv == 0) {
#pragma unroll
                for (int i = 0; i < 4; i++) sacc[i][j] = -1e10f;
            }
        }
#pragma unroll
        for (int i = 0; i < 4; i++) {
            float rmax = fmaxf(fmaxf(sacc[i][0], sacc[i][1]), fmaxf(sacc[i][2], sacc[i][3]));
#pragma unroll
            for (int off = 8; off; off >>= 1)
                rmax = fmaxf(rmax, __shfl_xor_sync(0xffffffffu, rmax, off));
            float mn = fmaxf(m_i[i], rmax);
            float corr = __expf(m_i[i] - mn);
            m_i[i] = mn;
            float rsum = 0.0f;
#pragma unroll
            for (int j = 0; j < 4; j++) {
                float p = __expf(sacc[i][j] - mn);
                sacc[i][j] = p;
                rsum += p;
            }
#pragma unroll
            for (int off = 8; off; off >>= 1)
                rsum += __shfl_xor_sync(0xffffffffu, rsum, off);
            l_i[i] = l_i[i] * corr + rsum;
#pragma unroll
            for (int j = 0; j < 4; j++) o[i][j] *= corr;
        }
#pragma unroll
        for (int j = 0; j < 4; j++)
#pragma unroll
            for (int i = 0; i < 4; i++)
                Pt[(tx * 4 + j) * AST + ty * 4 + i] = sacc[i][j];
        __syncthreads();
#pragma unroll 16
        for (int kk = 0; kk < 64; kk++) {
            float4 a = *(const float4*)&Pt[kk * AST + ty * 4];
            float4 bb = *(const float4*)&Vs[kk * AST + tx * 4];
            float av[4] = {a.x, a.y, a.z, a.w};
            float bv[4] = {bb.x, bb.y, bb.z, bb.w};
#pragma unroll
            for (int i = 0; i < 4; i++)
#pragma unroll
                for (int j = 0; j < 4; j++) o[i][j] += av[i] * bv[j];
        }
        __syncthreads();
    }
#pragma unroll
    for (int i = 0; i < 4; i++) {
        float rl = 1.0f / l_i[i];
        float4 ov;
        ov.x = o[i][0] * rl; ov.y = o[i][1] * rl; ov.z = o[i][2] * rl; ov.w = o[i][3] * rl;
        *(float4*)&vbar[((size_t)(b * SEQ + q0 + ty * 4 + i) * DMODEL) + h * DHEAD + tx * 4] = ov;
    }
}

// ---------------- KAN inner ----------------
__device__ __forceinline__ float2 bspline01(float x) {
    const float h = 2.0f / 7.0f;
    const float i1 = 3.5f;
    const float i2 = 1.75f;
    const float i3 = 7.0f / 6.0f;
    float B0[5];
#pragma unroll
    for (int kk = 0; kk < 5; kk++) {
        float tk = -1.0f + kk * h;
        B0[kk] = (x >= tk && x < tk + h) ? 1.0f : 0.0f;
    }
    float B1[4];
#pragma unroll
    for (int kk = 0; kk < 4; kk++) {
        float tk = -1.0f + kk * h;
        B1[kk] = (x - tk) * i1 * B0[kk] + ((tk + 2.0f * h) - x) * i1 * B0[kk + 1];
    }
    float B2[3];
#pragma unroll
    for (int kk = 0; kk < 3; kk++) {
        float tk = -1.0f + kk * h;
        B2[kk] = (x - tk) * i2 * B1[kk] + ((tk + 3.0f * h) - x) * i2 * B1[kk + 1];
    }
    float2 r;
    {
        float tk = -1.0f;
        r.x = (x - tk) * i3 * B2[0] + ((tk + 4.0f * h) - x) * i3 * B2[1];
        tk = -1.0f + h;
        r.y = (x - tk) * i3 * B2[1] + ((tk + 4.0f * h) - x) * i3 * B2[2];
    }
    return r;
}

__global__ void kan_inner_kernel(const float* __restrict__ z,
                                 const float* __restrict__ ic,
                                 float* __restrict__ inner) {
    int idx = blockIdx.x * blockDim.x + threadIdx.x;
    int d = idx & (DMODEL - 1);
    float x = tanhf(z[idx]);
    float2 bs = bspline01(x);
    inner[idx] = bs.x * ic[d * 5 + 0] + bs.y * ic[d * 5 + 1];
}

// ---------------- host ----------------
extern "C" void kernel_launch(void* const* d_in, const int* in_sizes, int n_in,
                              void* d_out, int out_size) {
    const float* src    = (const float*)d_in[0];
    const float* ln1_w  = (const float*)d_in[1];
    const float* ln1_b  = (const float*)d_in[2];
    const float* ln2_w  = (const float*)d_in[3];
    const float* ln2_b  = (const float*)d_in[4];
    const float* ln3_w  = (const float*)d_in[5];
    const float* ln3_b  = (const float*)d_in[6];
    const float* Wq_w   = (const float*)d_in[7];
    const float* Wq_b   = (const float*)d_in[8];
    const float* Wk_w   = (const float*)d_in[9];
    const float* Wk_b   = (const float*)d_in[10];
    const float* Wv_w   = (const float*)d_in[11];
    const float* Wv_b   = (const float*)d_in[12];
    const float* Wr_w   = (const float*)d_in[13];
    const float* Wr_b   = (const float*)d_in[14];
    const float* Wo_w   = (const float*)d_in[15];
    const float* Wo_b   = (const float*)d_in[16];
    const float* inner_c= (const float*)d_in[17];
    const float* outer_c= (const float*)d_in[18];
    const int*   mask   = (const int*)d_in[19];
    float* out = (float*)d_out;

    float *z, *q, *k, *v, *r, *vb, *inner;
    __nv_bfloat16 *wh, *wl, *ah, *al;
    cudaGetSymbolAddress((void**)&z, g_z);
    cudaGetSymbolAddress((void**)&q, g_q);
    cudaGetSymbolAddress((void**)&k, g_k);
    cudaGetSymbolAddress((void**)&v, g_v);
    cudaGetSymbolAddress((void**)&r, g_r);
    cudaGetSymbolAddress((void**)&vb, g_vb);
    cudaGetSymbolAddress((void**)&inner, g_inner);
    cudaGetSymbolAddress((void**)&wh, g_wh);
    cudaGetSymbolAddress((void**)&wl, g_wl);
    cudaGetSymbolAddress((void**)&ah, g_ah);
    cudaGetSymbolAddress((void**)&al, g_al);

    cudaFuncSetAttribute(attn_kernel, cudaFuncAttributeMaxDynamicSharedMemorySize,
                         ATT_SMEM_BYTES);
    cudaFuncSetAttribute(mma_gemm<true, false>,
                         cudaFuncAttributeMaxDynamicSharedMemorySize, GEMM_SMEM);
    cudaFuncSetAttribute(mma_gemm<true, true>,
                         cudaFuncAttributeMaxDynamicSharedMemorySize, GEMM_SMEM);
    cudaFuncSetAttribute(mma_gemm<false, true>,
                         cudaFuncAttributeMaxDynamicSharedMemorySize, GEMM_SMEM);

    // convert all weights to bf16 hi/lo once per launch
    // layout: type t (0=Wq,1=Wk,2=Wv,3=Wr,4=Wo,5=outer), layer l -> (t*4 + l)*MAT
    {
        int n4 = 4 * MAT / 4;
        int blocks = (n4 + 255) / 256;
        split_kernel<<<blocks, 256>>>(Wq_w,   wh + (size_t)0 * 4 * MAT, wl + (size_t)0 * 4 * MAT, n4);
        split_kernel<<<blocks, 256>>>(Wk_w,   wh + (size_t)1 * 4 * MAT, wl + (size_t)1 * 4 * MAT, n4);
        split_kernel<<<blocks, 256>>>(Wv_w,   wh + (size_t)2 * 4 * MAT, wl + (size_t)2 * 4 * MAT, n4);
        split_kernel<<<blocks, 256>>>(Wr_w,   wh + (size_t)3 * 4 * MAT, wl + (size_t)3 * 4 * MAT, n4);
        split_kernel<<<blocks, 256>>>(Wo_w,   wh + (size_t)4 * 4 * MAT, wl + (size_t)4 * 4 * MAT, n4);
        split_kernel<<<blocks, 256>>>(outer_c, wh + (size_t)5 * 4 * MAT, wl + (size_t)5 * 4 * MAT, n4);
    }

    cudaMemcpyAsync(out, src, (size_t)ROWS * DMODEL * sizeof(float),
                    cudaMemcpyDeviceToDevice, 0);

    const int an4 = ROWS * DMODEL / 4;
    const int ablocks = (an4 + 255) / 256;
    dim3 ggrid(DMODEL / 128, ROWS / 128);

    for (int l = 0; l < NLAYER; l++) {
#define WPTR(t) (wh + ((size_t)(t) * 4 + l) * MAT)
#define WPTRL(t) (wl + ((size_t)(t) * 4 + l) * MAT)
        // --- attention block ---
        ln_kernel<<<ROWS, 128>>>(out, ln1_w + l * DMODEL, ln1_b + l * DMODEL, z);
        split_kernel<<<ablocks, 256>>>(z, ah, al, an4);
        mma_gemm<true, false><<<ggrid, 256, GEMM_SMEM>>>(ah, al, WPTR(0), WPTRL(0), Wq_b + l * DMODEL, nullptr, q);
        mma_gemm<true, false><<<ggrid, 256, GEMM_SMEM>>>(ah, al, WPTR(1), WPTRL(1), Wk_b + l * DMODEL, nullptr, k);
        mma_gemm<true, false><<<ggrid, 256, GEMM_SMEM>>>(ah, al, WPTR(2), WPTRL(2), Wv_b + l * DMODEL, nullptr, v);
        mma_gemm<true, false><<<ggrid, 256, GEMM_SMEM>>>(ah, al, WPTR(3), WPTRL(3), Wr_b + l * DMODEL, nullptr, r);
        attn_kernel<<<dim3(SEQ / 64, NHEAD, BSZ), 256, ATT_SMEM_BYTES>>>(q, k, v, mask, vb);
        // src = src + (vbar * R) @ Wo^T + Wo_b
        mul_split_kernel<<<ablocks, 256>>>(vb, r, ah, al, an4);
        mma_gemm<true, true><<<ggrid, 256, GEMM_SMEM>>>(ah, al, WPTR(4), WPTRL(4), Wo_b + l * DMODEL, out, out);
        // --- KAN block ---
        ln_kernel<<<ROWS, 128>>>(out, ln2_w + l * DMODEL, ln2_b + l * DMODEL, z);
        kan_inner_kernel<<<ROWS * DMODEL / 256, 256>>>(z, inner_c + l * DMODEL * 5, inner);
        split_kernel<<<ablocks, 256>>>(inner, ah, al, an4);
        mma_gemm<false, true><<<ggrid, 256, GEMM_SMEM>>>(ah, al, WPTR(5), WPTRL(5), nullptr, out, out);
        ln_kernel<<<ROWS, 128>>>(out, ln3_w + l * DMODEL, ln3_b + l * DMODEL, out);
#undef WPTR
#undef WPTRL
    }
}

// round 6
// speedup vs baseline: 1.8258x; 1.3952x over previous
#include <cuda_runtime.h>
#include <cuda_bf16.h>
#include <math.h>
#include <stdint.h>

// Problem constants
#define BSZ 4
#define SEQ 1024
#define DMODEL 512
#define NHEAD 8
#define DHEAD 64
#define NLAYER 4
#define ROWS (BSZ * SEQ)          // 4096
#define MAT (DMODEL * DMODEL)     // 262144

// ---------------- scratch (device globals; no allocation) ----------------
__device__ float g_z[ROWS * DMODEL];
__device__ float g_r[ROWS * DMODEL];
__device__ float g_vb[ROWS * DMODEL];
__device__ float g_inner[ROWS * DMODEL];
// bf16 split buffers
__device__ __nv_bfloat16 g_wh[24 * MAT];
__device__ __nv_bfloat16 g_wl[24 * MAT];
__device__ __nv_bfloat16 g_ah[ROWS * DMODEL];
__device__ __nv_bfloat16 g_al[ROWS * DMODEL];
// attention operand buffers (bf16 hi/lo), layout [b*SEQ+s][h*64+d]
__device__ __nv_bfloat16 g_qh[ROWS * DMODEL];
__device__ __nv_bfloat16 g_ql[ROWS * DMODEL];
__device__ __nv_bfloat16 g_kh[ROWS * DMODEL];
__device__ __nv_bfloat16 g_kl[ROWS * DMODEL];
__device__ __nv_bfloat16 g_vh[ROWS * DMODEL];
__device__ __nv_bfloat16 g_vl[ROWS * DMODEL];

// ---------------- PTX helpers (sm_80+ features only) ----------------
__device__ __forceinline__ uint32_t smem_to_u32(const void* p) {
    uint32_t a;
    asm("{ .reg .u64 t; cvta.to.shared.u64 t, %1; cvt.u32.u64 %0, t; }" : "=r"(a) : "l"(p));
    return a;
}
__device__ __forceinline__ void cp_async16(uint32_t dst, const void* src) {
    asm volatile("cp.async.cg.shared.global [%0], [%1], 16;" :: "r"(dst), "l"(src));
}
__device__ __forceinline__ void ldsm4(uint32_t& r0, uint32_t& r1, uint32_t& r2, uint32_t& r3,
                                      uint32_t a) {
    asm volatile("ldmatrix.sync.aligned.m8n8.x4.shared.b16 {%0,%1,%2,%3}, [%4];"
                 : "=r"(r0), "=r"(r1), "=r"(r2), "=r"(r3) : "r"(a));
}
__device__ __forceinline__ void mma16816(float* c, uint32_t a0, uint32_t a1, uint32_t a2,
                                         uint32_t a3, uint32_t b0, uint32_t b1) {
    asm volatile(
        "mma.sync.aligned.m16n8k16.row.col.f32.bf16.bf16.f32 "
        "{%0,%1,%2,%3}, {%4,%5,%6,%7}, {%8,%9}, {%0,%1,%2,%3};"
        : "+f"(c[0]), "+f"(c[1]), "+f"(c[2]), "+f"(c[3])
        : "r"(a0), "r"(a1), "r"(a2), "r"(a3), "r"(b0), "r"(b1));
}

// ---------------- LayerNorm ----------------
__inline__ __device__ float warp_sum(float v) {
#pragma unroll
    for (int o = 16; o; o >>= 1) v += __shfl_xor_sync(0xffffffffu, v, o);
    return v;
}

__global__ void ln_kernel(const float* __restrict__ x,
                          const float* __restrict__ w,
                          const float* __restrict__ b,
                          float* __restrict__ y) {
    int row = blockIdx.x;
    int t = threadIdx.x;
    const float4 v = *(const float4*)&x[(size_t)row * DMODEL + t * 4];
    float s  = v.x + v.y + v.z + v.w;
    float sq = v.x * v.x + v.y * v.y + v.z * v.z + v.w * v.w;
    __shared__ float red[8];
    float s1 = warp_sum(s), s2 = warp_sum(sq);
    int warp = t >> 5, lane = t & 31;
    if (lane == 0) { red[warp] = s1; red[4 + warp] = s2; }
    __syncthreads();
    s1 = red[0] + red[1] + red[2] + red[3];
    s2 = red[4] + red[5] + red[6] + red[7];
    float mu = s1 * (1.0f / DMODEL);
    float var = s2 * (1.0f / DMODEL) - mu * mu;
    float inv = rsqrtf(var + 1e-5f);
    const float4 wv = *(const float4*)&w[t * 4];
    const float4 bv = *(const float4*)&b[t * 4];
    float4 o;
    o.x = (v.x - mu) * inv * wv.x + bv.x;
    o.y = (v.y - mu) * inv * wv.y + bv.y;
    o.z = (v.z - mu) * inv * wv.z + bv.z;
    o.w = (v.w - mu) * inv * wv.w + bv.w;
    *(float4*)&y[(size_t)row * DMODEL + t * 4] = o;
}

// ---------------- fp32 -> bf16 hi/lo split ----------------
__device__ __forceinline__ void split_store(float v, __nv_bfloat16* hi, __nv_bfloat16* lo) {
    __nv_bfloat16 h = __float2bfloat16(v);
    *hi = h;
    *lo = __float2bfloat16(v - __bfloat162float(h));
}

__global__ void split_kernel(const float* __restrict__ x,
                             __nv_bfloat16* __restrict__ hi,
                             __nv_bfloat16* __restrict__ lo, int n4) {
    int i = blockIdx.x * blockDim.x + threadIdx.x;
    if (i >= n4) return;
    float4 v = ((const float4*)x)[i];
    __nv_bfloat16 hv[4], lv[4];
    split_store(v.x, &hv[0], &lv[0]);
    split_store(v.y, &hv[1], &lv[1]);
    split_store(v.z, &hv[2], &lv[2]);
    split_store(v.w, &hv[3], &lv[3]);
    ((uint64_t*)hi)[i] = *(uint64_t*)hv;
    ((uint64_t*)lo)[i] = *(uint64_t*)lv;
}

__global__ void mul_split_kernel(const float* __restrict__ a, const float* __restrict__ b,
                                 __nv_bfloat16* __restrict__ hi,
                                 __nv_bfloat16* __restrict__ lo, int n4) {
    int i = blockIdx.x * blockDim.x + threadIdx.x;
    if (i >= n4) return;
    float4 va = ((const float4*)a)[i];
    float4 vb = ((const float4*)b)[i];
    __nv_bfloat16 hv[4], lv[4];
    split_store(va.x * vb.x, &hv[0], &lv[0]);
    split_store(va.y * vb.y, &hv[1], &lv[1]);
    split_store(va.z * vb.z, &hv[2], &lv[2]);
    split_store(va.w * vb.w, &hv[3], &lv[3]);
    ((uint64_t*)hi)[i] = *(uint64_t*)hv;
    ((uint64_t*)lo)[i] = *(uint64_t*)lv;
}

// ---------------- mma.sync bf16 GEMM core (3-split) ----------------
#define GEMM_SMEM 65536
#define NCHUNK 24

// shared mainloop: leaves acc[4][4][4] filled. OUT: 0 = fp32 (+bias)(+res), 1 = split bf16 (*scale,+bias)
template <bool BIAS, bool RES, int OUT>
__global__ __launch_bounds__(256, 1)
void mma_gemm(const __nv_bfloat16* __restrict__ ah, const __nv_bfloat16* __restrict__ al,
              const __nv_bfloat16* __restrict__ wh, const __nv_bfloat16* __restrict__ wl,
              const float* __restrict__ bias, const float* __restrict__ res,
              float* __restrict__ C,
              __nv_bfloat16* __restrict__ Chi, __nv_bfloat16* __restrict__ Clo,
              float scale) {
    extern __shared__ char smem[];
    const uint32_t smb = smem_to_u32(smem);
    const int tid = threadIdx.x;
    const int wid = tid >> 5, lane = tid & 31;
    const int n0 = blockIdx.x * 128, m0 = blockIdx.y * 128;
    const int wm = (wid >> 2) * 64;
    const int wn = (wid & 3) * 32;

    float acc[4][4][4];
#pragma unroll
    for (int i = 0; i < 4; i++)
#pragma unroll
        for (int j = 0; j < 4; j++)
#pragma unroll
            for (int q = 0; q < 4; q++) acc[i][j][q] = 0.0f;

    auto stage = [&](int c, int s) {
        int sp = c >> 3, kc = (c & 7) * 64;
        const __nv_bfloat16* asrc = (sp == 2) ? al : ah;
        const __nv_bfloat16* wsrc = (sp == 1) ? wl : wh;
        int row = tid >> 1;
        int g0 = (tid & 1) * 4;
        const char* ga = (const char*)(asrc + (size_t)(m0 + row) * DMODEL + kc);
        const char* gw = (const char*)(wsrc + (size_t)(n0 + row) * DMODEL + kc);
        uint32_t sa = smb + s * 32768 + row * 128;
        uint32_t sb = sa + 16384;
#pragma unroll
        for (int j = 0; j < 4; j++) {
            int g = g0 + j;
            uint32_t so = (uint32_t)((g ^ (row & 7)) << 4);
            cp_async16(sa + so, ga + g * 16);
            cp_async16(sb + so, gw + g * 16);
        }
    };

    auto compute = [&](int s) {
        uint32_t Abase = smb + s * 32768;
        uint32_t Bbase = Abase + 16384;
#pragma unroll
        for (int k16 = 0; k16 < 4; k16++) {
            uint32_t a[4][4];
#pragma unroll
            for (int mi = 0; mi < 4; mi++) {
                int row = wm + mi * 16 + (lane & 15);
                int g = k16 * 2 + (lane >> 4);
                uint32_t addr = Abase + row * 128 + ((g ^ (row & 7)) << 4);
                ldsm4(a[mi][0], a[mi][1], a[mi][2], a[mi][3], addr);
            }
            uint32_t b[2][4];
#pragma unroll
            for (int nj = 0; nj < 2; nj++) {
                int row = wn + nj * 16 + ((lane >> 4) << 3) + (lane & 7);
                int g = k16 * 2 + ((lane >> 3) & 1);
                uint32_t addr = Bbase + row * 128 + ((g ^ (row & 7)) << 4);
                ldsm4(b[nj][0], b[nj][1], b[nj][2], b[nj][3], addr);
            }
#pragma unroll
            for (int mi = 0; mi < 4; mi++)
#pragma unroll
                for (int ni = 0; ni < 4; ni++)
                    mma16816(acc[mi][ni], a[mi][0], a[mi][1], a[mi][2], a[mi][3],
                             b[ni >> 1][(ni & 1) * 2], b[ni >> 1][(ni & 1) * 2 + 1]);
        }
    };

    stage(0, 0);
    asm volatile("cp.async.commit_group;");
    stage(1, 1);
    asm volatile("cp.async.commit_group;");

    for (int c = 0; c < NCHUNK; c++) {
        if (c < NCHUNK - 1) asm volatile("cp.async.wait_group 1;");
        else                asm volatile("cp.async.wait_group 0;");
        __syncthreads();
        compute(c & 1);
        __syncthreads();
        if (c + 2 < NCHUNK) {
            stage(c + 2, c & 1);
            asm volatile("cp.async.commit_group;");
        }
    }

    const int lr = lane >> 2;
    const int lc = (lane & 3) * 2;
#pragma unroll
    for (int mi = 0; mi < 4; mi++) {
#pragma unroll
        for (int ni = 0; ni < 4; ni++) {
            int col = n0 + wn + ni * 8 + lc;
            float bx = 0.0f, by = 0.0f;
            if (BIAS) { bx = bias[col]; by = bias[col + 1]; }
            int row0 = m0 + wm + mi * 16 + lr;
            float v[4];
            v[0] = acc[mi][ni][0] + bx; v[1] = acc[mi][ni][1] + by;
            v[2] = acc[mi][ni][2] + bx; v[3] = acc[mi][ni][3] + by;
            size_t o0 = (size_t)row0 * DMODEL + col;
            size_t o1 = (size_t)(row0 + 8) * DMODEL + col;
            if (OUT == 0) {
                if (RES) {
                    float2 r0 = *(const float2*)&res[o0];
                    float2 r1 = *(const float2*)&res[o1];
                    v[0] += r0.x; v[1] += r0.y; v[2] += r1.x; v[3] += r1.y;
                }
                *(float2*)&C[o0] = make_float2(v[0], v[1]);
                *(float2*)&C[o1] = make_float2(v[2], v[3]);
            } else {
                __nv_bfloat16 hv[4], lv[4];
#pragma unroll
                for (int q = 0; q < 4; q++) {
                    float sv = v[q] * scale;
                    __nv_bfloat16 hh = __float2bfloat16(sv);
                    hv[q] = hh;
                    lv[q] = __float2bfloat16(sv - __bfloat162float(hh));
                }
                *(uint32_t*)&Chi[o0] = *(uint32_t*)&hv[0];
                *(uint32_t*)&Chi[o1] = *(uint32_t*)&hv[2];
                *(uint32_t*)&Clo[o0] = *(uint32_t*)&lv[0];
                *(uint32_t*)&Clo[o1] = *(uint32_t*)&lv[2];
            }
        }
    }
}

// ---------------- mma flash attention (bf16 3-split, fp32 softmax) ----------------
// CTA: 128 q rows x (h, b). 8 warps x m16. KV in blocks of 64.
// smem: Kh@0(8K) Kl@8K Vth@16K Vtl@24K  (Q staged at 0..32K before loop), mask @32K.
#define AT_SMEM (32768 + 256)

__global__ __launch_bounds__(256, 1)
void attn_mma(const __nv_bfloat16* __restrict__ qh, const __nv_bfloat16* __restrict__ ql,
              const __nv_bfloat16* __restrict__ kh, const __nv_bfloat16* __restrict__ kl,
              const __nv_bfloat16* __restrict__ vh, const __nv_bfloat16* __restrict__ vl,
              const int* __restrict__ mask, float* __restrict__ vbar) {
    extern __shared__ char smem[];
    const uint32_t smb = smem_to_u32(smem);
    int* msk = (int*)(smem + 32768);
    const int tid = threadIdx.x;
    const int wid = tid >> 5, lane = tid & 31;
    const int b = blockIdx.z, h = blockIdx.y, q0 = blockIdx.x * 128;
    const int wm = wid * 16;
    const int lr = lane >> 2;
    const int lc = (lane & 3) * 2;

    // ---- stage Q (hi @0, lo @16384), 128 rows x 128B each ----
    {
        int row = tid >> 1;
        int g0 = (tid & 1) * 4;
        size_t gofs = (size_t)(b * SEQ + q0 + row) * DMODEL + h * DHEAD;
        const char* gqh = (const char*)(qh + gofs);
        const char* gql = (const char*)(ql + gofs);
        uint32_t srow = smb + row * 128;
#pragma unroll
        for (int j = 0; j < 4; j++) {
            int g = g0 + j;
            uint32_t so = (uint32_t)((g ^ (row & 7)) << 4);
            cp_async16(srow + so, gqh + g * 16);
            cp_async16(srow + 16384 + so, gql + g * 16);
        }
    }
    asm volatile("cp.async.commit_group;");
    asm volatile("cp.async.wait_group 0;");
    __syncthreads();

    // ---- load Q fragments into registers ----
    uint32_t Qh_[4][4], Ql_[4][4];
    {
        int row = wm + (lane & 15);
#pragma unroll
        for (int k16 = 0; k16 < 4; k16++) {
            int g = k16 * 2 + (lane >> 4);
            uint32_t so = (uint32_t)(row * 128 + ((g ^ (row & 7)) << 4));
            ldsm4(Qh_[k16][0], Qh_[k16][1], Qh_[k16][2], Qh_[k16][3], smb + so);
            ldsm4(Ql_[k16][0], Ql_[k16][1], Ql_[k16][2], Ql_[k16][3], smb + 16384 + so);
        }
    }
    __syncthreads();   // Q smem free for KV reuse

    float Of[8][4];
#pragma unroll
    for (int i = 0; i < 8; i++)
#pragma unroll
        for (int q = 0; q < 4; q++) Of[i][q] = 0.0f;
    float m0r = -1e30f, m1r = -1e30f, l0 = 0.0f, l1 = 0.0f;

    for (int jt = 0; jt < SEQ / 64; jt++) {
        const int kv0 = jt * 64;
        // stage K (cp.async): 64 rows x 128B x 2 mats
        {
            int r = tid >> 2;
            int g0 = tid & 3;
            size_t gofs = (size_t)(b * SEQ + kv0 + r) * DMODEL + h * DHEAD;
            const char* gkh = (const char*)(kh + gofs);
            const char* gkl = (const char*)(kl + gofs);
            uint32_t srow = smb + r * 128;
#pragma unroll
            for (int t = 0; t < 2; t++) {
                int g = g0 + t * 4;
                uint32_t so = (uint32_t)((g ^ (r & 7)) << 4);
                cp_async16(srow + so, gkh + g * 16);
                cp_async16(srow + 8192 + so, gkl + g * 16);
            }
        }
        asm volatile("cp.async.commit_group;");
        // stage V transposed (Vt[d][kv]) via LDG + STS
        {
            int c = tid & 63;
            int dp0 = tid >> 6;
            size_t gofs = (size_t)(b * SEQ + kv0 + c) * DMODEL + h * DHEAD;
#pragma unroll
            for (int i = 0; i < 8; i++) {
                int d = (dp0 + i * 4) * 2;
                uint32_t wv = *(const uint32_t*)&vh[gofs + d];
                uint32_t wl_ = *(const uint32_t*)&vl[gofs + d];
                int off0 = d * 128 + ((((c >> 3) ^ (d & 7)) << 4)) + (c & 7) * 2;
                int off1 = (d + 1) * 128 + ((((c >> 3) ^ ((d + 1) & 7)) << 4)) + (c & 7) * 2;
                *(uint16_t*)(smem + 16384 + off0) = (uint16_t)(wv & 0xffff);
                *(uint16_t*)(smem + 16384 + off1) = (uint16_t)(wv >> 16);
                *(uint16_t*)(smem + 24576 + off0) = (uint16_t)(wl_ & 0xffff);
                *(uint16_t*)(smem + 24576 + off1) = (uint16_t)(wl_ >> 16);
            }
        }
        if (tid < 64) msk[tid] = mask[b * SEQ + kv0 + tid];
        asm volatile("cp.async.wait_group 0;");
        __syncthreads();

        // ---- S = Qh*Kh + Qh*Kl + Ql*Kh  (warp: 16 rows x 64 kv) ----
        float S[8][4];
#pragma unroll
        for (int i = 0; i < 8; i++)
#pragma unroll
            for (int q = 0; q < 4; q++) S[i][q] = 0.0f;
#pragma unroll
        for (int k16 = 0; k16 < 4; k16++) {
#pragma unroll
            for (int nj = 0; nj < 4; nj++) {
                int row = nj * 16 + ((lane >> 4) << 3) + (lane & 7);
                int g = k16 * 2 + ((lane >> 3) & 1);
                uint32_t so = (uint32_t)(row * 128 + ((g ^ (row & 7)) << 4));
                uint32_t bh0, bh1, bh2, bh3, bl0, bl1, bl2, bl3;
                ldsm4(bh0, bh1, bh2, bh3, smb + so);
                ldsm4(bl0, bl1, bl2, bl3, smb + 8192 + so);
                mma16816(S[2 * nj], Qh_[k16][0], Qh_[k16][1], Qh_[k16][2], Qh_[k16][3], bh0, bh1);
                mma16816(S[2 * nj], Qh_[k16][0], Qh_[k16][1], Qh_[k16][2], Qh_[k16][3], bl0, bl1);
                mma16816(S[2 * nj], Ql_[k16][0], Ql_[k16][1], Ql_[k16][2], Ql_[k16][3], bh0, bh1);
                mma16816(S[2 * nj + 1], Qh_[k16][0], Qh_[k16][1], Qh_[k16][2], Qh_[k16][3], bh2, bh3);
                mma16816(S[2 * nj + 1], Qh_[k16][0], Qh_[k16][1], Qh_[k16][2], Qh_[k16][3], bl2, bl3);
                mma16816(S[2 * nj + 1], Ql_[k16][0], Ql_[k16][1], Ql_[k16][2], Ql_[k16][3], bh2, bh3);
            }
        }
        // ---- mask + online softmax (rows lr, lr+8 within warp) ----
#pragma unroll
        for (int ni = 0; ni < 8; ni++) {
            int j0 = ni * 8 + lc;
            if (msk[j0] == 0)     { S[ni][0] = -1e10f; S[ni][2] = -1e10f; }
            if (msk[j0 + 1] == 0) { S[ni][1] = -1e10f; S[ni][3] = -1e10f; }
        }
        float rmax0 = -1e30f, rmax1 = -1e30f;
#pragma unroll
        for (int ni = 0; ni < 8; ni++) {
            rmax0 = fmaxf(rmax0, fmaxf(S[ni][0], S[ni][1]));
            rmax1 = fmaxf(rmax1, fmaxf(S[ni][2], S[ni][3]));
        }
        rmax0 = fmaxf(rmax0, __shfl_xor_sync(0xffffffffu, rmax0, 1));
        rmax0 = fmaxf(rmax0, __shfl_xor_sync(0xffffffffu, rmax0, 2));
        rmax1 = fmaxf(rmax1, __shfl_xor_sync(0xffffffffu, rmax1, 1));
        rmax1 = fmaxf(rmax1, __shfl_xor_sync(0xffffffffu, rmax1, 2));
        float mn0 = fmaxf(m0r, rmax0), mn1 = fmaxf(m1r, rmax1);
        float corr0 = __expf(m0r - mn0), corr1 = __expf(m1r - mn1);
        m0r = mn0; m1r = mn1;
        float rs0 = 0.0f, rs1 = 0.0f;
#pragma unroll
        for (int ni = 0; ni < 8; ni++) {
            S[ni][0] = __expf(S[ni][0] - mn0); rs0 += S[ni][0];
            S[ni][1] = __expf(S[ni][1] - mn0); rs0 += S[ni][1];
            S[ni][2] = __expf(S[ni][2] - mn1); rs1 += S[ni][2];
            S[ni][3] = __expf(S[ni][3] - mn1); rs1 += S[ni][3];
        }
        rs0 += __shfl_xor_sync(0xffffffffu, rs0, 1);
        rs0 += __shfl_xor_sync(0xffffffffu, rs0, 2);
        rs1 += __shfl_xor_sync(0xffffffffu, rs1, 1);
        rs1 += __shfl_xor_sync(0xffffffffu, rs1, 2);
        l0 = l0 * corr0 + rs0;
        l1 = l1 * corr1 + rs1;
#pragma unroll
        for (int ni = 0; ni < 8; ni++) {
            Of[ni][0] *= corr0; Of[ni][1] *= corr0;
            Of[ni][2] *= corr1; Of[ni][3] *= corr1;
        }
        // ---- O += Ph*Vh + Ph*Vl + Pl*Vh ----
#pragma unroll
        for (int k16 = 0; k16 < 4; k16++) {
            // P A-fragments from registers (C-frag -> A-frag identity)
            float2 f0 = make_float2(S[2 * k16][0], S[2 * k16][1]);
            float2 f1 = make_float2(S[2 * k16][2], S[2 * k16][3]);
            float2 f2 = make_float2(S[2 * k16 + 1][0], S[2 * k16 + 1][1]);
            float2 f3 = make_float2(S[2 * k16 + 1][2], S[2 * k16 + 1][3]);
            __nv_bfloat162 h0 = __float22bfloat162_rn(f0);
            __nv_bfloat162 h1 = __float22bfloat162_rn(f1);
            __nv_bfloat162 h2 = __float22bfloat162_rn(f2);
            __nv_bfloat162 h3 = __float22bfloat162_rn(f3);
            __nv_bfloat162 e0 = __float22bfloat162_rn(make_float2(f0.x - __low2float(h0), f0.y - __high2float(h0)));
            __nv_bfloat162 e1 = __float22bfloat162_rn(make_float2(f1.x - __low2float(h1), f1.y - __high2float(h1)));
            __nv_bfloat162 e2 = __float22bfloat162_rn(make_float2(f2.x - __low2float(h2), f2.y - __high2float(h2)));
            __nv_bfloat162 e3 = __float22bfloat162_rn(make_float2(f3.x - __low2float(h3), f3.y - __high2float(h3)));
            uint32_t ah0 = *(uint32_t*)&h0, ah1 = *(uint32_t*)&h1, ah2 = *(uint32_t*)&h2, ah3 = *(uint32_t*)&h3;
            uint32_t al0 = *(uint32_t*)&e0, al1 = *(uint32_t*)&e1, al2 = *(uint32_t*)&e2, al3 = *(uint32_t*)&e3;
#pragma unroll
            for (int nj = 0; nj < 4; nj++) {
                int row = nj * 16 + ((lane >> 4) << 3) + (lane & 7);
                int g = k16 * 2 + ((lane >> 3) & 1);
                uint32_t so = (uint32_t)(row * 128 + ((g ^ (row & 7)) << 4));
                uint32_t vh0, vh1, vh2, vh3, vl0, vl1, vl2, vl3;
                ldsm4(vh0, vh1, vh2, vh3, smb + 16384 + so);
                ldsm4(vl0, vl1, vl2, vl3, smb + 24576 + so);
                mma16816(Of[2 * nj], ah0, ah1, ah2, ah3, vh0, vh1);
                mma16816(Of[2 * nj], ah0, ah1, ah2, ah3, vl0, vl1);
                mma16816(Of[2 * nj], al0, al1, al2, al3, vh0, vh1);
                mma16816(Of[2 * nj + 1], ah0, ah1, ah2, ah3, vh2, vh3);
                mma16816(Of[2 * nj + 1], ah0, ah1, ah2, ah3, vl2, vl3);
                mma16816(Of[2 * nj + 1], al0, al1, al2, al3, vh2, vh3);
            }
        }
        __syncthreads();  // before restaging next block
    }

    // ---- epilogue ----
    float inv0 = 1.0f / l0, inv1 = 1.0f / l1;
    int r0 = b * SEQ + q0 + wm + lr;
    int r1 = r0 + 8;
#pragma unroll
    for (int ni = 0; ni < 8; ni++) {
        int col = h * DHEAD + ni * 8 + lc;
        *(float2*)&vbar[(size_t)r0 * DMODEL + col] = make_float2(Of[ni][0] * inv0, Of[ni][1] * inv0);
        *(float2*)&vbar[(size_t)r1 * DMODEL + col] = make_float2(Of[ni][2] * inv1, Of[ni][3] * inv1);
    }
}

// ---------------- KAN inner ----------------
__device__ __forceinline__ float2 bspline01(float x) {
    const float h = 2.0f / 7.0f;
    const float i1 = 3.5f;
    const float i2 = 1.75f;
    const float i3 = 7.0f / 6.0f;
    float B0[5];
#pragma unroll
    for (int kk = 0; kk < 5; kk++) {
        float tk = -1.0f + kk * h;
        B0[kk] = (x >= tk && x < tk + h) ? 1.0f : 0.0f;
    }
    float B1[4];
#pragma unroll
    for (int kk = 0; kk < 4; kk++) {
        float tk = -1.0f + kk * h;
        B1[kk] = (x - tk) * i1 * B0[kk] + ((tk + 2.0f * h) - x) * i1 * B0[kk + 1];
    }
    float B2[3];
#pragma unroll
    for (int kk = 0; kk < 3; kk++) {
        float tk = -1.0f + kk * h;
        B2[kk] = (x - tk) * i2 * B1[kk] + ((tk + 3.0f * h) - x) * i2 * B1[kk + 1];
    }
    float2 r;
    {
        float tk = -1.0f;
        r.x = (x - tk) * i3 * B2[0] + ((tk + 4.0f * h) - x) * i3 * B2[1];
        tk = -1.0f + h;
        r.y = (x - tk) * i3 * B2[1] + ((tk + 4.0f * h) - x) * i3 * B2[2];
    }
    return r;
}

__global__ void kan_inner_kernel(const float* __restrict__ z,
                                 const float* __restrict__ ic,
                                 float* __restrict__ inner) {
    int idx = blockIdx.x * blockDim.x + threadIdx.x;
    int d = idx & (DMODEL - 1);
    float x = tanhf(z[idx]);
    float2 bs = bspline01(x);
    inner[idx] = bs.x * ic[d * 5 + 0] + bs.y * ic[d * 5 + 1];
}

// ---------------- host ----------------
extern "C" void kernel_launch(void* const* d_in, const int* in_sizes, int n_in,
                              void* d_out, int out_size) {
    const float* src    = (const float*)d_in[0];
    const float* ln1_w  = (const float*)d_in[1];
    const float* ln1_b  = (const float*)d_in[2];
    const float* ln2_w  = (const float*)d_in[3];
    const float* ln2_b  = (const float*)d_in[4];
    const float* ln3_w  = (const float*)d_in[5];
    const float* ln3_b  = (const float*)d_in[6];
    const float* Wq_w   = (const float*)d_in[7];
    const float* Wq_b   = (const float*)d_in[8];
    const float* Wk_w   = (const float*)d_in[9];
    const float* Wk_b   = (const float*)d_in[10];
    const float* Wv_w   = (const float*)d_in[11];
    const float* Wv_b   = (const float*)d_in[12];
    const float* Wr_w   = (const float*)d_in[13];
    const float* Wr_b   = (const float*)d_in[14];
    const float* Wo_w   = (const float*)d_in[15];
    const float* Wo_b   = (const float*)d_in[16];
    const float* inner_c= (const float*)d_in[17];
    const float* outer_c= (const float*)d_in[18];
    const int*   mask   = (const int*)d_in[19];
    float* out = (float*)d_out;

    float *z, *r, *vb, *inner;
    __nv_bfloat16 *wh, *wl, *ah, *al, *qh, *ql, *kh, *kl, *vh, *vl;
    cudaGetSymbolAddress((void**)&z, g_z);
    cudaGetSymbolAddress((void**)&r, g_r);
    cudaGetSymbolAddress((void**)&vb, g_vb);
    cudaGetSymbolAddress((void**)&inner, g_inner);
    cudaGetSymbolAddress((void**)&wh, g_wh);
    cudaGetSymbolAddress((void**)&wl, g_wl);
    cudaGetSymbolAddress((void**)&ah, g_ah);
    cudaGetSymbolAddress((void**)&al, g_al);
    cudaGetSymbolAddress((void**)&qh, g_qh);
    cudaGetSymbolAddress((void**)&ql, g_ql);
    cudaGetSymbolAddress((void**)&kh, g_kh);
    cudaGetSymbolAddress((void**)&kl, g_kl);
    cudaGetSymbolAddress((void**)&vh, g_vh);
    cudaGetSymbolAddress((void**)&vl, g_vl);

    cudaFuncSetAttribute(attn_mma, cudaFuncAttributeMaxDynamicSharedMemorySize, AT_SMEM);
    cudaFuncSetAttribute(mma_gemm<true, false, 0>, cudaFuncAttributeMaxDynamicSharedMemorySize, GEMM_SMEM);
    cudaFuncSetAttribute(mma_gemm<true, true, 0>, cudaFuncAttributeMaxDynamicSharedMemorySize, GEMM_SMEM);
    cudaFuncSetAttribute(mma_gemm<false, true, 0>, cudaFuncAttributeMaxDynamicSharedMemorySize, GEMM_SMEM);
    cudaFuncSetAttribute(mma_gemm<true, false, 1>, cudaFuncAttributeMaxDynamicSharedMemorySize, GEMM_SMEM);

    // weights -> bf16 hi/lo, once per launch
    {
        int n4 = 4 * MAT / 4;
        int blocks = (n4 + 255) / 256;
        split_kernel<<<blocks, 256>>>(Wq_w,    wh + (size_t)0 * 4 * MAT, wl + (size_t)0 * 4 * MAT, n4);
        split_kernel<<<blocks, 256>>>(Wk_w,    wh + (size_t)1 * 4 * MAT, wl + (size_t)1 * 4 * MAT, n4);
        split_kernel<<<blocks, 256>>>(Wv_w,    wh + (size_t)2 * 4 * MAT, wl + (size_t)2 * 4 * MAT, n4);
        split_kernel<<<blocks, 256>>>(Wr_w,    wh + (size_t)3 * 4 * MAT, wl + (size_t)3 * 4 * MAT, n4);
        split_kernel<<<blocks, 256>>>(Wo_w,    wh + (size_t)4 * 4 * MAT, wl + (size_t)4 * 4 * MAT, n4);
        split_kernel<<<blocks, 256>>>(outer_c, wh + (size_t)5 * 4 * MAT, wl + (size_t)5 * 4 * MAT, n4);
    }

    cudaMemcpyAsync(out, src, (size_t)ROWS * DMODEL * sizeof(float),
                    cudaMemcpyDeviceToDevice, 0);

    const int an4 = ROWS * DMODEL / 4;
    const int ablocks = (an4 + 255) / 256;
    dim3 ggrid(DMODEL / 128, ROWS / 128);

    for (int l = 0; l < NLAYER; l++) {
#define WH(t) (wh + ((size_t)(t) * 4 + l) * MAT)
#define WL(t) (wl + ((size_t)(t) * 4 + l) * MAT)
        // --- attention block ---
        ln_kernel<<<ROWS, 128>>>(out, ln1_w + l * DMODEL, ln1_b + l * DMODEL, z);
        split_kernel<<<ablocks, 256>>>(z, ah, al, an4);
        mma_gemm<true, false, 1><<<ggrid, 256, GEMM_SMEM>>>(ah, al, WH(0), WL(0), Wq_b + l * DMODEL, nullptr, nullptr, qh, ql, 0.125f);
        mma_gemm<true, false, 1><<<ggrid, 256, GEMM_SMEM>>>(ah, al, WH(1), WL(1), Wk_b + l * DMODEL, nullptr, nullptr, kh, kl, 1.0f);
        mma_gemm<true, false, 1><<<ggrid, 256, GEMM_SMEM>>>(ah, al, WH(2), WL(2), Wv_b + l * DMODEL, nullptr, nullptr, vh, vl, 1.0f);
        mma_gemm<true, false, 0><<<ggrid, 256, GEMM_SMEM>>>(ah, al, WH(3), WL(3), Wr_b + l * DMODEL, nullptr, r, nullptr, nullptr, 1.0f);
        attn_mma<<<dim3(SEQ / 128, NHEAD, BSZ), 256, AT_SMEM>>>(qh, ql, kh, kl, vh, vl, mask, vb);
        // src = src + (vbar * R) @ Wo^T + Wo_b
        mul_split_kernel<<<ablocks, 256>>>(vb, r, ah, al, an4);
        mma_gemm<true, true, 0><<<ggrid, 256, GEMM_SMEM>>>(ah, al, WH(4), WL(4), Wo_b + l * DMODEL, out, out, nullptr, nullptr, 1.0f);
        // --- KAN block ---
        ln_kernel<<<ROWS, 128>>>(out, ln2_w + l * DMODEL, ln2_b + l * DMODEL, z);
        kan_inner_kernel<<<ROWS * DMODEL / 256, 256>>>(z, inner_c + l * DMODEL * 5, inner);
        split_kernel<<<ablocks, 256>>>(inner, ah, al, an4);
        mma_gemm<false, true, 0><<<ggrid, 256, GEMM_SMEM>>>(ah, al, WH(5), WL(5), nullptr, out, out, nullptr, nullptr, 1.0f);
        ln_kernel<<<ROWS, 128>>>(out, ln3_w + l * DMODEL, ln3_b + l * DMODEL, out);
#undef WH
#undef WL
    }
}

// round 7
// speedup vs baseline: 1.8851x; 1.0325x over previous
#include <cuda_runtime.h>
#include <cuda_bf16.h>
#include <math.h>
#include <stdint.h>

// Problem constants
#define BSZ 4
#define SEQ 1024
#define DMODEL 512
#define NHEAD 8
#define DHEAD 64
#define NLAYER 4
#define ROWS (BSZ * SEQ)          // 4096
#define MAT (DMODEL * DMODEL)     // 262144

// ---------------- scratch (device globals; no allocation) ----------------
__device__ float g_z[ROWS * DMODEL];
__device__ float g_r[ROWS * DMODEL];
__device__ float g_vb[ROWS * DMODEL];
// bf16 split buffers. Weight layout: QKVR fused per layer at (4l+t)*MAT,
// Wo at (16+l)*MAT, outer at (20+l)*MAT.
__device__ __nv_bfloat16 g_wh[24 * MAT];
__device__ __nv_bfloat16 g_wl[24 * MAT];
__device__ __nv_bfloat16 g_ah[ROWS * DMODEL];
__device__ __nv_bfloat16 g_al[ROWS * DMODEL];
// attention operand buffers (bf16 hi/lo), layout [b*SEQ+s][h*64+d]
__device__ __nv_bfloat16 g_qh[ROWS * DMODEL];
__device__ __nv_bfloat16 g_ql[ROWS * DMODEL];
__device__ __nv_bfloat16 g_kh[ROWS * DMODEL];
__device__ __nv_bfloat16 g_kl[ROWS * DMODEL];
__device__ __nv_bfloat16 g_vh[ROWS * DMODEL];
__device__ __nv_bfloat16 g_vl[ROWS * DMODEL];

// ---------------- PTX helpers (sm_80+ features only) ----------------
__device__ __forceinline__ uint32_t smem_to_u32(const void* p) {
    uint32_t a;
    asm("{ .reg .u64 t; cvta.to.shared.u64 t, %1; cvt.u32.u64 %0, t; }" : "=r"(a) : "l"(p));
    return a;
}
__device__ __forceinline__ void cp_async16(uint32_t dst, const void* src) {
    asm volatile("cp.async.cg.shared.global [%0], [%1], 16;" :: "r"(dst), "l"(src));
}
__device__ __forceinline__ void ldsm4(uint32_t& r0, uint32_t& r1, uint32_t& r2, uint32_t& r3,
                                      uint32_t a) {
    asm volatile("ldmatrix.sync.aligned.m8n8.x4.shared.b16 {%0,%1,%2,%3}, [%4];"
                 : "=r"(r0), "=r"(r1), "=r"(r2), "=r"(r3) : "r"(a));
}
__device__ __forceinline__ void mma16816(float* c, uint32_t a0, uint32_t a1, uint32_t a2,
                                         uint32_t a3, uint32_t b0, uint32_t b1) {
    asm volatile(
        "mma.sync.aligned.m16n8k16.row.col.f32.bf16.bf16.f32 "
        "{%0,%1,%2,%3}, {%4,%5,%6,%7}, {%8,%9}, {%0,%1,%2,%3};"
        : "+f"(c[0]), "+f"(c[1]), "+f"(c[2]), "+f"(c[3])
        : "r"(a0), "r"(a1), "r"(a2), "r"(a3), "r"(b0), "r"(b1));
}

__device__ __forceinline__ void split_store(float v, __nv_bfloat16* hi, __nv_bfloat16* lo) {
    __nv_bfloat16 h = __float2bfloat16(v);
    *hi = h;
    *lo = __float2bfloat16(v - __bfloat162float(h));
}

// ---------------- LayerNorm helpers ----------------
__inline__ __device__ float warp_sum(float v) {
#pragma unroll
    for (int o = 16; o; o >>= 1) v += __shfl_xor_sync(0xffffffffu, v, o);
    return v;
}

__device__ __forceinline__ float4 ln_row(const float* __restrict__ x,
                                         const float* __restrict__ w,
                                         const float* __restrict__ b,
                                         int row, int t) {
    const float4 v = *(const float4*)&x[(size_t)row * DMODEL + t * 4];
    float s  = v.x + v.y + v.z + v.w;
    float sq = v.x * v.x + v.y * v.y + v.z * v.z + v.w * v.w;
    __shared__ float red[8];
    float s1 = warp_sum(s), s2 = warp_sum(sq);
    int warp = t >> 5, lane = t & 31;
    if (lane == 0) { red[warp] = s1; red[4 + warp] = s2; }
    __syncthreads();
    s1 = red[0] + red[1] + red[2] + red[3];
    s2 = red[4] + red[5] + red[6] + red[7];
    float mu = s1 * (1.0f / DMODEL);
    float var = s2 * (1.0f / DMODEL) - mu * mu;
    float inv = rsqrtf(var + 1e-5f);
    const float4 wv = *(const float4*)&w[t * 4];
    const float4 bv = *(const float4*)&b[t * 4];
    float4 o;
    o.x = (v.x - mu) * inv * wv.x + bv.x;
    o.y = (v.y - mu) * inv * wv.y + bv.y;
    o.z = (v.z - mu) * inv * wv.z + bv.z;
    o.w = (v.w - mu) * inv * wv.w + bv.w;
    return o;
}

__global__ void ln_kernel(const float* __restrict__ x,
                          const float* __restrict__ w,
                          const float* __restrict__ b,
                          float* __restrict__ y) {
    int row = blockIdx.x, t = threadIdx.x;
    float4 o = ln_row(x, w, b, row, t);
    *(float4*)&y[(size_t)row * DMODEL + t * 4] = o;
}

// LN fused with bf16 hi/lo split output
__global__ void ln_split_kernel(const float* __restrict__ x,
                                const float* __restrict__ w,
                                const float* __restrict__ b,
                                __nv_bfloat16* __restrict__ hi,
                                __nv_bfloat16* __restrict__ lo) {
    int row = blockIdx.x, t = threadIdx.x;
    float4 o = ln_row(x, w, b, row, t);
    __nv_bfloat16 hv[4], lv[4];
    split_store(o.x, &hv[0], &lv[0]);
    split_store(o.y, &hv[1], &lv[1]);
    split_store(o.z, &hv[2], &lv[2]);
    split_store(o.w, &hv[3], &lv[3]);
    int i = row * (DMODEL / 4) + t;
    ((uint64_t*)hi)[i] = *(uint64_t*)hv;
    ((uint64_t*)lo)[i] = *(uint64_t*)lv;
}

// ---------------- weight prep: all 24 matrices -> fused bf16 hi/lo ----------------
__global__ void weight_prep(const float* __restrict__ Wq, const float* __restrict__ Wk,
                            const float* __restrict__ Wv, const float* __restrict__ Wr,
                            const float* __restrict__ Wo, const float* __restrict__ Oc,
                            __nv_bfloat16* __restrict__ wh, __nv_bfloat16* __restrict__ wl) {
    int i = blockIdx.x * blockDim.x + threadIdx.x;   // float4 index
    const int per = MAT / 4;
    if (i >= 24 * per) return;
    int s = i / per;
    int off = i - s * per;
    const float* src;
    if (s < 16) {
        int l = s >> 2, t = s & 3;
        src = (t == 0 ? Wq : t == 1 ? Wk : t == 2 ? Wv : Wr) + (size_t)l * MAT;
    } else if (s < 20) {
        src = Wo + (size_t)(s - 16) * MAT;
    } else {
        src = Oc + (size_t)(s - 20) * MAT;
    }
    float4 v = ((const float4*)src)[off];
    __nv_bfloat16 hv[4], lv[4];
    split_store(v.x, &hv[0], &lv[0]);
    split_store(v.y, &hv[1], &lv[1]);
    split_store(v.z, &hv[2], &lv[2]);
    split_store(v.w, &hv[3], &lv[3]);
    ((uint64_t*)wh)[i] = *(uint64_t*)hv;
    ((uint64_t*)wl)[i] = *(uint64_t*)lv;
}

__global__ void mul_split_kernel(const float* __restrict__ a, const float* __restrict__ b,
                                 __nv_bfloat16* __restrict__ hi,
                                 __nv_bfloat16* __restrict__ lo, int n4) {
    int i = blockIdx.x * blockDim.x + threadIdx.x;
    if (i >= n4) return;
    float4 va = ((const float4*)a)[i];
    float4 vb = ((const float4*)b)[i];
    __nv_bfloat16 hv[4], lv[4];
    split_store(va.x * vb.x, &hv[0], &lv[0]);
    split_store(va.y * vb.y, &hv[1], &lv[1]);
    split_store(va.z * vb.z, &hv[2], &lv[2]);
    split_store(va.w * vb.w, &hv[3], &lv[3]);
    ((uint64_t*)hi)[i] = *(uint64_t*)hv;
    ((uint64_t*)lo)[i] = *(uint64_t*)lv;
}

// ---------------- shared GEMM mainloop machinery ----------------
#define GEMM_SMEM 65536
#define NCHUNK 24

// Stage chunk c of A (rows m0..m0+127) and W (rows n0..n0+127, row-stride DMODEL) into stage s.
__device__ __forceinline__ void gemm_stage(uint32_t smb, int tid, int m0, int n0, int c, int s,
                                           const __nv_bfloat16* ah, const __nv_bfloat16* al,
                                           const __nv_bfloat16* wh, const __nv_bfloat16* wl) {
    int sp = c >> 3, kc = (c & 7) * 64;
    const __nv_bfloat16* asrc = (sp == 2) ? al : ah;
    const __nv_bfloat16* wsrc = (sp == 1) ? wl : wh;
    int row = tid >> 1;
    int g0 = (tid & 1) * 4;
    const char* ga = (const char*)(asrc + (size_t)(m0 + row) * DMODEL + kc);
    const char* gw = (const char*)(wsrc + (size_t)(n0 + row) * DMODEL + kc);
    uint32_t sa = smb + s * 32768 + row * 128;
    uint32_t sb = sa + 16384;
#pragma unroll
    for (int j = 0; j < 4; j++) {
        int g = g0 + j;
        uint32_t so = (uint32_t)((g ^ (row & 7)) << 4);
        cp_async16(sa + so, ga + g * 16);
        cp_async16(sb + so, gw + g * 16);
    }
}

__device__ __forceinline__ void gemm_compute(uint32_t smb, int s, int wm, int wn, int lane,
                                             float acc[4][4][4]) {
    uint32_t Abase = smb + s * 32768;
    uint32_t Bbase = Abase + 16384;
#pragma unroll
    for (int k16 = 0; k16 < 4; k16++) {
        uint32_t a[4][4];
#pragma unroll
        for (int mi = 0; mi < 4; mi++) {
            int row = wm + mi * 16 + (lane & 15);
            int g = k16 * 2 + (lane >> 4);
            uint32_t addr = Abase + row * 128 + ((g ^ (row & 7)) << 4);
            ldsm4(a[mi][0], a[mi][1], a[mi][2], a[mi][3], addr);
        }
        uint32_t b[2][4];
#pragma unroll
        for (int nj = 0; nj < 2; nj++) {
            int row = wn + nj * 16 + ((lane >> 4) << 3) + (lane & 7);
            int g = k16 * 2 + ((lane >> 3) & 1);
            uint32_t addr = Bbase + row * 128 + ((g ^ (row & 7)) << 4);
            ldsm4(b[nj][0], b[nj][1], b[nj][2], b[nj][3], addr);
        }
#pragma unroll
        for (int mi = 0; mi < 4; mi++)
#pragma unroll
            for (int ni = 0; ni < 4; ni++)
                mma16816(acc[mi][ni], a[mi][0], a[mi][1], a[mi][2], a[mi][3],
                         b[ni >> 1][(ni & 1) * 2], b[ni >> 1][(ni & 1) * 2 + 1]);
    }
}

#define GEMM_MAINLOOP(AH, AL, WHp, WLp, M0, N0)                                  \
    gemm_stage(smb, tid, M0, N0, 0, 0, AH, AL, WHp, WLp);                        \
    asm volatile("cp.async.commit_group;");                                      \
    gemm_stage(smb, tid, M0, N0, 1, 1, AH, AL, WHp, WLp);                        \
    asm volatile("cp.async.commit_group;");                                      \
    for (int c = 0; c < NCHUNK; c++) {                                           \
        if (c < NCHUNK - 1) asm volatile("cp.async.wait_group 1;");              \
        else                asm volatile("cp.async.wait_group 0;");              \
        __syncthreads();                                                         \
        gemm_compute(smb, c & 1, wm, wn, lane, acc);                             \
        __syncthreads();                                                         \
        if (c + 2 < NCHUNK) {                                                    \
            gemm_stage(smb, tid, M0, N0, c + 2, c & 1, AH, AL, WHp, WLp);        \
            asm volatile("cp.async.commit_group;");                              \
        }                                                                        \
    }

// ---------------- standard GEMM (fp32 out, +bias +res) ----------------
template <bool BIAS, bool RES>
__global__ __launch_bounds__(256, 1)
void mma_gemm(const __nv_bfloat16* __restrict__ ah, const __nv_bfloat16* __restrict__ al,
              const __nv_bfloat16* __restrict__ wh, const __nv_bfloat16* __restrict__ wl,
              const float* __restrict__ bias, const float* __restrict__ res,
              float* __restrict__ C) {
    extern __shared__ char smem[];
    const uint32_t smb = smem_to_u32(smem);
    const int tid = threadIdx.x;
    const int wid = tid >> 5, lane = tid & 31;
    const int n0 = blockIdx.x * 128, m0 = blockIdx.y * 128;
    const int wm = (wid >> 2) * 64;
    const int wn = (wid & 3) * 32;

    float acc[4][4][4];
#pragma unroll
    for (int i = 0; i < 4; i++)
#pragma unroll
        for (int j = 0; j < 4; j++)
#pragma unroll
            for (int q = 0; q < 4; q++) acc[i][j][q] = 0.0f;

    GEMM_MAINLOOP(ah, al, wh, wl, m0, n0)

    const int lr = lane >> 2;
    const int lc = (lane & 3) * 2;
#pragma unroll
    for (int mi = 0; mi < 4; mi++) {
#pragma unroll
        for (int ni = 0; ni < 4; ni++) {
            int col = n0 + wn + ni * 8 + lc;
            float bx = 0.0f, by = 0.0f;
            if (BIAS) { bx = bias[col]; by = bias[col + 1]; }
            int row0 = m0 + wm + mi * 16 + lr;
            float v[4];
            v[0] = acc[mi][ni][0] + bx; v[1] = acc[mi][ni][1] + by;
            v[2] = acc[mi][ni][2] + bx; v[3] = acc[mi][ni][3] + by;
            size_t o0 = (size_t)row0 * DMODEL + col;
            size_t o1 = (size_t)(row0 + 8) * DMODEL + col;
            if (RES) {
                float2 r0 = *(const float2*)&res[o0];
                float2 r1 = *(const float2*)&res[o1];
                v[0] += r0.x; v[1] += r0.y; v[2] += r1.x; v[3] += r1.y;
            }
            *(float2*)&C[o0] = make_float2(v[0], v[1]);
            *(float2*)&C[o1] = make_float2(v[2], v[3]);
        }
    }
}

// ---------------- fused QKVR GEMM: N=2048 (4 types x 512) ----------------
// blockIdx.x 0..15; type = blockIdx.x>>2 (0=Q,1=K,2=V,3=R); col block within type = (blockIdx.x&3)*128.
__global__ __launch_bounds__(256, 1)
void qkvr_gemm(const __nv_bfloat16* __restrict__ ah, const __nv_bfloat16* __restrict__ al,
               const __nv_bfloat16* __restrict__ wh, const __nv_bfloat16* __restrict__ wl,
               const float* __restrict__ bq, const float* __restrict__ bk,
               const float* __restrict__ bv, const float* __restrict__ br,
               __nv_bfloat16* __restrict__ qh, __nv_bfloat16* __restrict__ ql,
               __nv_bfloat16* __restrict__ kh, __nv_bfloat16* __restrict__ kl,
               __nv_bfloat16* __restrict__ vhp, __nv_bfloat16* __restrict__ vlp,
               float* __restrict__ rr) {
    extern __shared__ char smem[];
    const uint32_t smb = smem_to_u32(smem);
    const int tid = threadIdx.x;
    const int wid = tid >> 5, lane = tid & 31;
    const int n0 = blockIdx.x * 128, m0 = blockIdx.y * 128;
    const int wm = (wid >> 2) * 64;
    const int wn = (wid & 3) * 32;

    float acc[4][4][4];
#pragma unroll
    for (int i = 0; i < 4; i++)
#pragma unroll
        for (int j = 0; j < 4; j++)
#pragma unroll
            for (int q = 0; q < 4; q++) acc[i][j][q] = 0.0f;

    GEMM_MAINLOOP(ah, al, wh, wl, m0, n0)

    const int type = blockIdx.x >> 2;
    const int ncol0 = (blockIdx.x & 3) * 128;   // col within 512
    const float* bias = (type == 0) ? bq : (type == 1) ? bk : (type == 2) ? bv : br;
    const float scale = (type == 0) ? 0.125f : 1.0f;
    __nv_bfloat16* Hi = (type == 0) ? qh : (type == 1) ? kh : vhp;
    __nv_bfloat16* Lo = (type == 0) ? ql : (type == 1) ? kl : vlp;

    const int lr = lane >> 2;
    const int lc = (lane & 3) * 2;
#pragma unroll
    for (int mi = 0; mi < 4; mi++) {
#pragma unroll
        for (int ni = 0; ni < 4; ni++) {
            int col = ncol0 + wn + ni * 8 + lc;
            float bx = bias[col], by = bias[col + 1];
            int row0 = m0 + wm + mi * 16 + lr;
            float v[4];
            v[0] = acc[mi][ni][0] + bx; v[1] = acc[mi][ni][1] + by;
            v[2] = acc[mi][ni][2] + bx; v[3] = acc[mi][ni][3] + by;
            size_t o0 = (size_t)row0 * DMODEL + col;
            size_t o1 = (size_t)(row0 + 8) * DMODEL + col;
            if (type == 3) {
                *(float2*)&rr[o0] = make_float2(v[0], v[1]);
                *(float2*)&rr[o1] = make_float2(v[2], v[3]);
            } else {
                __nv_bfloat16 hv[4], lv[4];
#pragma unroll
                for (int q = 0; q < 4; q++) {
                    float sv = v[q] * scale;
                    __nv_bfloat16 hh = __float2bfloat16(sv);
                    hv[q] = hh;
                    lv[q] = __float2bfloat16(sv - __bfloat162float(hh));
                }
                *(uint32_t*)&Hi[o0] = *(uint32_t*)&hv[0];
                *(uint32_t*)&Hi[o1] = *(uint32_t*)&hv[2];
                *(uint32_t*)&Lo[o0] = *(uint32_t*)&lv[0];
                *(uint32_t*)&Lo[o1] = *(uint32_t*)&lv[2];
            }
        }
    }
}

// ---------------- mma flash attention (bf16 3-split, fp32 softmax) ----------------
#define AT_SMEM (32768 + 256)

__global__ __launch_bounds__(256, 1)
void attn_mma(const __nv_bfloat16* __restrict__ qh, const __nv_bfloat16* __restrict__ ql,
              const __nv_bfloat16* __restrict__ kh, const __nv_bfloat16* __restrict__ kl,
              const __nv_bfloat16* __restrict__ vh, const __nv_bfloat16* __restrict__ vl,
              const int* __restrict__ mask, float* __restrict__ vbar) {
    extern __shared__ char smem[];
    const uint32_t smb = smem_to_u32(smem);
    int* msk = (int*)(smem + 32768);
    const int tid = threadIdx.x;
    const int wid = tid >> 5, lane = tid & 31;
    const int b = blockIdx.z, h = blockIdx.y, q0 = blockIdx.x * 128;
    const int wm = wid * 16;
    const int lr = lane >> 2;
    const int lc = (lane & 3) * 2;

    // ---- stage Q (hi @0, lo @16384) ----
    {
        int row = tid >> 1;
        int g0 = (tid & 1) * 4;
        size_t gofs = (size_t)(b * SEQ + q0 + row) * DMODEL + h * DHEAD;
        const char* gqh = (const char*)(qh + gofs);
        const char* gql = (const char*)(ql + gofs);
        uint32_t srow = smb + row * 128;
#pragma unroll
        for (int j = 0; j < 4; j++) {
            int g = g0 + j;
            uint32_t so = (uint32_t)((g ^ (row & 7)) << 4);
            cp_async16(srow + so, gqh + g * 16);
            cp_async16(srow + 16384 + so, gql + g * 16);
        }
    }
    asm volatile("cp.async.commit_group;");
    asm volatile("cp.async.wait_group 0;");
    __syncthreads();

    uint32_t Qh_[4][4], Ql_[4][4];
    {
        int row = wm + (lane & 15);
#pragma unroll
        for (int k16 = 0; k16 < 4; k16++) {
            int g = k16 * 2 + (lane >> 4);
            uint32_t so = (uint32_t)(row * 128 + ((g ^ (row & 7)) << 4));
            ldsm4(Qh_[k16][0], Qh_[k16][1], Qh_[k16][2], Qh_[k16][3], smb + so);
            ldsm4(Ql_[k16][0], Ql_[k16][1], Ql_[k16][2], Ql_[k16][3], smb + 16384 + so);
        }
    }
    __syncthreads();

    float Of[8][4];
#pragma unroll
    for (int i = 0; i < 8; i++)
#pragma unroll
        for (int q = 0; q < 4; q++) Of[i][q] = 0.0f;
    float m0r = -1e30f, m1r = -1e30f, l0 = 0.0f, l1 = 0.0f;

    for (int jt = 0; jt < SEQ / 64; jt++) {
        const int kv0 = jt * 64;
        {
            int r = tid >> 2;
            int g0 = tid & 3;
            size_t gofs = (size_t)(b * SEQ + kv0 + r) * DMODEL + h * DHEAD;
            const char* gkh = (const char*)(kh + gofs);
            const char* gkl = (const char*)(kl + gofs);
            uint32_t srow = smb + r * 128;
#pragma unroll
            for (int t = 0; t < 2; t++) {
                int g = g0 + t * 4;
                uint32_t so = (uint32_t)((g ^ (r & 7)) << 4);
                cp_async16(srow + so, gkh + g * 16);
                cp_async16(srow + 8192 + so, gkl + g * 16);
            }
        }
        asm volatile("cp.async.commit_group;");
        // stage V transposed (Vt[d][kv]) via LDG + STS
        {
            int c = tid & 63;
            int dp0 = tid >> 6;
            size_t gofs = (size_t)(b * SEQ + kv0 + c) * DMODEL + h * DHEAD;
#pragma unroll
            for (int i = 0; i < 8; i++) {
                int d = (dp0 + i * 4) * 2;
                uint32_t wv = *(const uint32_t*)&vh[gofs + d];
                uint32_t wl_ = *(const uint32_t*)&vl[gofs + d];
                int off0 = d * 128 + ((((c >> 3) ^ (d & 7)) << 4)) + (c & 7) * 2;
                int off1 = (d + 1) * 128 + ((((c >> 3) ^ ((d + 1) & 7)) << 4)) + (c & 7) * 2;
                *(uint16_t*)(smem + 16384 + off0) = (uint16_t)(wv & 0xffff);
                *(uint16_t*)(smem + 16384 + off1) = (uint16_t)(wv >> 16);
                *(uint16_t*)(smem + 24576 + off0) = (uint16_t)(wl_ & 0xffff);
                *(uint16_t*)(smem + 24576 + off1) = (uint16_t)(wl_ >> 16);
            }
        }
        if (tid < 64) msk[tid] = mask[b * SEQ + kv0 + tid];
        asm volatile("cp.async.wait_group 0;");
        __syncthreads();

        float S[8][4];
#pragma unroll
        for (int i = 0; i < 8; i++)
#pragma unroll
            for (int q = 0; q < 4; q++) S[i][q] = 0.0f;
#pragma unroll
        for (int k16 = 0; k16 < 4; k16++) {
#pragma unroll
            for (int nj = 0; nj < 4; nj++) {
                int row = nj * 16 + ((lane >> 4) << 3) + (lane & 7);
                int g = k16 * 2 + ((lane >> 3) & 1);
                uint32_t so = (uint32_t)(row * 128 + ((g ^ (row & 7)) << 4));
                uint32_t bh0, bh1, bh2, bh3, bl0, bl1, bl2, bl3;
                ldsm4(bh0, bh1, bh2, bh3, smb + so);
                ldsm4(bl0, bl1, bl2, bl3, smb + 8192 + so);
                mma16816(S[2 * nj], Qh_[k16][0], Qh_[k16][1], Qh_[k16][2], Qh_[k16][3], bh0, bh1);
                mma16816(S[2 * nj], Qh_[k16][0], Qh_[k16][1], Qh_[k16][2], Qh_[k16][3], bl0, bl1);
                mma16816(S[2 * nj], Ql_[k16][0], Ql_[k16][1], Ql_[k16][2], Ql_[k16][3], bh0, bh1);
                mma16816(S[2 * nj + 1], Qh_[k16][0], Qh_[k16][1], Qh_[k16][2], Qh_[k16][3], bh2, bh3);
                mma16816(S[2 * nj + 1], Qh_[k16][0], Qh_[k16][1], Qh_[k16][2], Qh_[k16][3], bl2, bl3);
                mma16816(S[2 * nj + 1], Ql_[k16][0], Ql_[k16][1], Ql_[k16][2], Ql_[k16][3], bh2, bh3);
            }
        }
#pragma unroll
        for (int ni = 0; ni < 8; ni++) {
            int j0 = ni * 8 + lc;
            if (msk[j0] == 0)     { S[ni][0] = -1e10f; S[ni][2] = -1e10f; }
            if (msk[j0 + 1] == 0) { S[ni][1] = -1e10f; S[ni][3] = -1e10f; }
        }
        float rmax0 = -1e30f, rmax1 = -1e30f;
#pragma unroll
        for (int ni = 0; ni < 8; ni++) {
            rmax0 = fmaxf(rmax0, fmaxf(S[ni][0], S[ni][1]));
            rmax1 = fmaxf(rmax1, fmaxf(S[ni][2], S[ni][3]));
        }
        rmax0 = fmaxf(rmax0, __shfl_xor_sync(0xffffffffu, rmax0, 1));
        rmax0 = fmaxf(rmax0, __shfl_xor_sync(0xffffffffu, rmax0, 2));
        rmax1 = fmaxf(rmax1, __shfl_xor_sync(0xffffffffu, rmax1, 1));
        rmax1 = fmaxf(rmax1, __shfl_xor_sync(0xffffffffu, rmax1, 2));
        float mn0 = fmaxf(m0r, rmax0), mn1 = fmaxf(m1r, rmax1);
        float corr0 = __expf(m0r - mn0), corr1 = __expf(m1r - mn1);
        m0r = mn0; m1r = mn1;
        float rs0 = 0.0f, rs1 = 0.0f;
#pragma unroll
        for (int ni = 0; ni < 8; ni++) {
            S[ni][0] = __expf(S[ni][0] - mn0); rs0 += S[ni][0];
            S[ni][1] = __expf(S[ni][1] - mn0); rs0 += S[ni][1];
            S[ni][2] = __expf(S[ni][2] - mn1); rs1 += S[ni][2];
            S[ni][3] = __expf(S[ni][3] - mn1); rs1 += S[ni][3];
        }
        rs0 += __shfl_xor_sync(0xffffffffu, rs0, 1);
        rs0 += __shfl_xor_sync(0xffffffffu, rs0, 2);
        rs1 += __shfl_xor_sync(0xffffffffu, rs1, 1);
        rs1 += __shfl_xor_sync(0xffffffffu, rs1, 2);
        l0 = l0 * corr0 + rs0;
        l1 = l1 * corr1 + rs1;
#pragma unroll
        for (int ni = 0; ni < 8; ni++) {
            Of[ni][0] *= corr0; Of[ni][1] *= corr0;
            Of[ni][2] *= corr1; Of[ni][3] *= corr1;
        }
#pragma unroll
        for (int k16 = 0; k16 < 4; k16++) {
            float2 f0 = make_float2(S[2 * k16][0], S[2 * k16][1]);
            float2 f1 = make_float2(S[2 * k16][2], S[2 * k16][3]);
            float2 f2 = make_float2(S[2 * k16 + 1][0], S[2 * k16 + 1][1]);
            float2 f3 = make_float2(S[2 * k16 + 1][2], S[2 * k16 + 1][3]);
            __nv_bfloat162 h0 = __float22bfloat162_rn(f0);
            __nv_bfloat162 h1 = __float22bfloat162_rn(f1);
            __nv_bfloat162 h2 = __float22bfloat162_rn(f2);
            __nv_bfloat162 h3 = __float22bfloat162_rn(f3);
            __nv_bfloat162 e0 = __float22bfloat162_rn(make_float2(f0.x - __low2float(h0), f0.y - __high2float(h0)));
            __nv_bfloat162 e1 = __float22bfloat162_rn(make_float2(f1.x - __low2float(h1), f1.y - __high2float(h1)));
            __nv_bfloat162 e2 = __float22bfloat162_rn(make_float2(f2.x - __low2float(h2), f2.y - __high2float(h2)));
            __nv_bfloat162 e3 = __float22bfloat162_rn(make_float2(f3.x - __low2float(h3), f3.y - __high2float(h3)));
            uint32_t ah0 = *(uint32_t*)&h0, ah1 = *(uint32_t*)&h1, ah2 = *(uint32_t*)&h2, ah3 = *(uint32_t*)&h3;
            uint32_t al0 = *(uint32_t*)&e0, al1 = *(uint32_t*)&e1, al2 = *(uint32_t*)&e2, al3 = *(uint32_t*)&e3;
#pragma unroll
            for (int nj = 0; nj < 4; nj++) {
                int row = nj * 16 + ((lane >> 4) << 3) + (lane & 7);
                int g = k16 * 2 + ((lane >> 3) & 1);
                uint32_t so = (uint32_t)(row * 128 + ((g ^ (row & 7)) << 4));
                uint32_t vh0, vh1, vh2, vh3, vl0, vl1, vl2, vl3;
                ldsm4(vh0, vh1, vh2, vh3, smb + 16384 + so);
                ldsm4(vl0, vl1, vl2, vl3, smb + 24576 + so);
                mma16816(Of[2 * nj], ah0, ah1, ah2, ah3, vh0, vh1);
                mma16816(Of[2 * nj], ah0, ah1, ah2, ah3, vl0, vl1);
                mma16816(Of[2 * nj], al0, al1, al2, al3, vh0, vh1);
                mma16816(Of[2 * nj + 1], ah0, ah1, ah2, ah3, vh2, vh3);
                mma16816(Of[2 * nj + 1], ah0, ah1, ah2, ah3, vl2, vl3);
                mma16816(Of[2 * nj + 1], al0, al1, al2, al3, vh2, vh3);
            }
        }
        __syncthreads();
    }

    float inv0 = 1.0f / l0, inv1 = 1.0f / l1;
    int r0 = b * SEQ + q0 + wm + lr;
    int r1 = r0 + 8;
#pragma unroll
    for (int ni = 0; ni < 8; ni++) {
        int col = h * DHEAD + ni * 8 + lc;
        *(float2*)&vbar[(size_t)r0 * DMODEL + col] = make_float2(Of[ni][0] * inv0, Of[ni][1] * inv0);
        *(float2*)&vbar[(size_t)r1 * DMODEL + col] = make_float2(Of[ni][2] * inv1, Of[ni][3] * inv1);
    }
}

// ---------------- KAN inner fused with split ----------------
__device__ __forceinline__ float2 bspline01(float x) {
    const float h = 2.0f / 7.0f;
    const float i1 = 3.5f;
    const float i2 = 1.75f;
    const float i3 = 7.0f / 6.0f;
    float B0[5];
#pragma unroll
    for (int kk = 0; kk < 5; kk++) {
        float tk = -1.0f + kk * h;
        B0[kk] = (x >= tk && x < tk + h) ? 1.0f : 0.0f;
    }
    float B1[4];
#pragma unroll
    for (int kk = 0; kk < 4; kk++) {
        float tk = -1.0f + kk * h;
        B1[kk] = (x - tk) * i1 * B0[kk] + ((tk + 2.0f * h) - x) * i1 * B0[kk + 1];
    }
    float B2[3];
#pragma unroll
    for (int kk = 0; kk < 3; kk++) {
        float tk = -1.0f + kk * h;
        B2[kk] = (x - tk) * i2 * B1[kk] + ((tk + 3.0f * h) - x) * i2 * B1[kk + 1];
    }
    float2 r;
    {
        float tk = -1.0f;
        r.x = (x - tk) * i3 * B2[0] + ((tk + 4.0f * h) - x) * i3 * B2[1];
        tk = -1.0f + h;
        r.y = (x - tk) * i3 * B2[1] + ((tk + 4.0f * h) - x) * i3 * B2[2];
    }
    return r;
}

__global__ void kan_split_kernel(const float* __restrict__ z,
                                 const float* __restrict__ ic,
                                 __nv_bfloat16* __restrict__ hi,
                                 __nv_bfloat16* __restrict__ lo) {
    int i = blockIdx.x * blockDim.x + threadIdx.x;   // float4 index
    float4 zv = ((const float4*)z)[i];
    int d0 = (i * 4) & (DMODEL - 1);
    __nv_bfloat16 hv[4], lv[4];
    float zz[4] = {zv.x, zv.y, zv.z, zv.w};
#pragma unroll
    for (int q = 0; q < 4; q++) {
        float x = tanhf(zz[q]);
        float2 bs = bspline01(x);
        int d = d0 + q;
        float val = bs.x * ic[d * 5 + 0] + bs.y * ic[d * 5 + 1];
        split_store(val, &hv[q], &lv[q]);
    }
    ((uint64_t*)hi)[i] = *(uint64_t*)hv;
    ((uint64_t*)lo)[i] = *(uint64_t*)lv;
}

// ---------------- host ----------------
extern "C" void kernel_launch(void* const* d_in, const int* in_sizes, int n_in,
                              void* d_out, int out_size) {
    const float* src    = (const float*)d_in[0];
    const float* ln1_w  = (const float*)d_in[1];
    const float* ln1_b  = (const float*)d_in[2];
    const float* ln2_w  = (const float*)d_in[3];
    const float* ln2_b  = (const float*)d_in[4];
    const float* ln3_w  = (const float*)d_in[5];
    const float* ln3_b  = (const float*)d_in[6];
    const float* Wq_w   = (const float*)d_in[7];
    const float* Wq_b   = (const float*)d_in[8];
    const float* Wk_w   = (const float*)d_in[9];
    const float* Wk_b   = (const float*)d_in[10];
    const float* Wv_w   = (const float*)d_in[11];
    const float* Wv_b   = (const float*)d_in[12];
    const float* Wr_w   = (const float*)d_in[13];
    const float* Wr_b   = (const float*)d_in[14];
    const float* Wo_w   = (const float*)d_in[15];
    const float* Wo_b   = (const float*)d_in[16];
    const float* inner_c= (const float*)d_in[17];
    const float* outer_c= (const float*)d_in[18];
    const int*   mask   = (const int*)d_in[19];
    float* out = (float*)d_out;

    float *z, *r, *vb;
    __nv_bfloat16 *wh, *wl, *ah, *al, *qh, *ql, *kh, *kl, *vh, *vl;
    cudaGetSymbolAddress((void**)&z, g_z);
    cudaGetSymbolAddress((void**)&r, g_r);
    cudaGetSymbolAddress((void**)&vb, g_vb);
    cudaGetSymbolAddress((void**)&wh, g_wh);
    cudaGetSymbolAddress((void**)&wl, g_wl);
    cudaGetSymbolAddress((void**)&ah, g_ah);
    cudaGetSymbolAddress((void**)&al, g_al);
    cudaGetSymbolAddress((void**)&qh, g_qh);
    cudaGetSymbolAddress((void**)&ql, g_ql);
    cudaGetSymbolAddress((void**)&kh, g_kh);
    cudaGetSymbolAddress((void**)&kl, g_kl);
    cudaGetSymbolAddress((void**)&vh, g_vh);
    cudaGetSymbolAddress((void**)&vl, g_vl);

    cudaFuncSetAttribute(attn_mma, cudaFuncAttributeMaxDynamicSharedMemorySize, AT_SMEM);
    cudaFuncSetAttribute(qkvr_gemm, cudaFuncAttributeMaxDynamicSharedMemorySize, GEMM_SMEM);
    cudaFuncSetAttribute(mma_gemm<true, true>, cudaFuncAttributeMaxDynamicSharedMemorySize, GEMM_SMEM);
    cudaFuncSetAttribute(mma_gemm<false, true>, cudaFuncAttributeMaxDynamicSharedMemorySize, GEMM_SMEM);

    // weights -> fused bf16 hi/lo, one launch
    {
        int n4 = 24 * MAT / 4;
        weight_prep<<<(n4 + 255) / 256, 256>>>(Wq_w, Wk_w, Wv_w, Wr_w, Wo_w, outer_c, wh, wl);
    }

    cudaMemcpyAsync(out, src, (size_t)ROWS * DMODEL * sizeof(float),
                    cudaMemcpyDeviceToDevice, 0);

    const int an4 = ROWS * DMODEL / 4;
    const int ablocks = (an4 + 255) / 256;
    dim3 ggrid(DMODEL / 128, ROWS / 128);
    dim3 qgrid(2048 / 128, ROWS / 128);

    for (int l = 0; l < NLAYER; l++) {
        const __nv_bfloat16* whQ = wh + (size_t)(4 * l) * MAT;
        const __nv_bfloat16* wlQ = wl + (size_t)(4 * l) * MAT;
        const __nv_bfloat16* whO = wh + (size_t)(16 + l) * MAT;
        const __nv_bfloat16* wlO = wl + (size_t)(16 + l) * MAT;
        const __nv_bfloat16* whC = wh + (size_t)(20 + l) * MAT;
        const __nv_bfloat16* wlC = wl + (size_t)(20 + l) * MAT;
        // --- attention block ---
        ln_split_kernel<<<ROWS, 128>>>(out, ln1_w + l * DMODEL, ln1_b + l * DMODEL, ah, al);
        qkvr_gemm<<<qgrid, 256, GEMM_SMEM>>>(ah, al, whQ, wlQ,
                                             Wq_b + l * DMODEL, Wk_b + l * DMODEL,
                                             Wv_b + l * DMODEL, Wr_b + l * DMODEL,
                                             qh, ql, kh, kl, vh, vl, r);
        attn_mma<<<dim3(SEQ / 128, NHEAD, BSZ), 256, AT_SMEM>>>(qh, ql, kh, kl, vh, vl, mask, vb);
        mul_split_kernel<<<ablocks, 256>>>(vb, r, ah, al, an4);
        mma_gemm<true, true><<<ggrid, 256, GEMM_SMEM>>>(ah, al, whO, wlO, Wo_b + l * DMODEL, out, out);
        // --- KAN block ---
        ln_kernel<<<ROWS, 128>>>(out, ln2_w + l * DMODEL, ln2_b + l * DMODEL, z);
        kan_split_kernel<<<ablocks, 256>>>(z, inner_c + l * DMODEL * 5, ah, al);
        mma_gemm<false, true><<<ggrid, 256, GEMM_SMEM>>>(ah, al, whC, wlC, nullptr, out, out);
        ln_kernel<<<ROWS, 128>>>(out, ln3_w + l * DMODEL, ln3_b + l * DMODEL, out);
    }
}

// round 8
// speedup vs baseline: 2.3515x; 1.2474x over previous
#include <cuda_runtime.h>
#include <cuda_bf16.h>
#include <math.h>
#include <stdint.h>

// Problem constants
#define BSZ 4
#define SEQ 1024
#define DMODEL 512
#define NHEAD 8
#define DHEAD 64
#define NLAYER 4
#define ROWS (BSZ * SEQ)          // 4096
#define MAT (DMODEL * DMODEL)     // 262144

// ---------------- scratch (device globals; no allocation) ----------------
__device__ float g_z[ROWS * DMODEL];
__device__ float g_r[ROWS * DMODEL];
__device__ float g_vb[ROWS * DMODEL];
// bf16 split buffers. Weight layout: QKVR fused per layer at (4l+t)*MAT,
// Wo at (16+l)*MAT, outer at (20+l)*MAT.
__device__ __nv_bfloat16 g_wh[24 * MAT];
__device__ __nv_bfloat16 g_wl[24 * MAT];
__device__ __nv_bfloat16 g_ah[ROWS * DMODEL];
__device__ __nv_bfloat16 g_al[ROWS * DMODEL];
// attention operand buffers (bf16 hi/lo), layout [b*SEQ+s][h*64+d]
__device__ __nv_bfloat16 g_qh[ROWS * DMODEL];
__device__ __nv_bfloat16 g_ql[ROWS * DMODEL];
__device__ __nv_bfloat16 g_kh[ROWS * DMODEL];
__device__ __nv_bfloat16 g_kl[ROWS * DMODEL];
__device__ __nv_bfloat16 g_vh[ROWS * DMODEL];
__device__ __nv_bfloat16 g_vl[ROWS * DMODEL];

// ---------------- PTX helpers (sm_80+ features only) ----------------
__device__ __forceinline__ uint32_t smem_to_u32(const void* p) {
    uint32_t a;
    asm("{ .reg .u64 t; cvta.to.shared.u64 t, %1; cvt.u32.u64 %0, t; }" : "=r"(a) : "l"(p));
    return a;
}
__device__ __forceinline__ void cp_async16(uint32_t dst, const void* src) {
    asm volatile("cp.async.cg.shared.global [%0], [%1], 16;" :: "r"(dst), "l"(src));
}
__device__ __forceinline__ void ldsm4(uint32_t& r0, uint32_t& r1, uint32_t& r2, uint32_t& r3,
                                      uint32_t a) {
    asm volatile("ldmatrix.sync.aligned.m8n8.x4.shared.b16 {%0,%1,%2,%3}, [%4];"
                 : "=r"(r0), "=r"(r1), "=r"(r2), "=r"(r3) : "r"(a));
}
__device__ __forceinline__ void ldsm4t(uint32_t& r0, uint32_t& r1, uint32_t& r2, uint32_t& r3,
                                       uint32_t a) {
    asm volatile("ldmatrix.sync.aligned.m8n8.x4.trans.shared.b16 {%0,%1,%2,%3}, [%4];"
                 : "=r"(r0), "=r"(r1), "=r"(r2), "=r"(r3) : "r"(a));
}
__device__ __forceinline__ void mma16816(float* c, uint32_t a0, uint32_t a1, uint32_t a2,
                                         uint32_t a3, uint32_t b0, uint32_t b1) {
    asm volatile(
        "mma.sync.aligned.m16n8k16.row.col.f32.bf16.bf16.f32 "
        "{%0,%1,%2,%3}, {%4,%5,%6,%7}, {%8,%9}, {%0,%1,%2,%3};"
        : "+f"(c[0]), "+f"(c[1]), "+f"(c[2]), "+f"(c[3])
        : "r"(a0), "r"(a1), "r"(a2), "r"(a3), "r"(b0), "r"(b1));
}

__device__ __forceinline__ void split_store(float v, __nv_bfloat16* hi, __nv_bfloat16* lo) {
    __nv_bfloat16 h = __float2bfloat16(v);
    *hi = h;
    *lo = __float2bfloat16(v - __bfloat162float(h));
}

// ---------------- LayerNorm helpers ----------------
__inline__ __device__ float warp_sum(float v) {
#pragma unroll
    for (int o = 16; o; o >>= 1) v += __shfl_xor_sync(0xffffffffu, v, o);
    return v;
}

__device__ __forceinline__ float4 ln_row(const float* __restrict__ x,
                                         const float* __restrict__ w,
                                         const float* __restrict__ b,
                                         int row, int t) {
    const float4 v = *(const float4*)&x[(size_t)row * DMODEL + t * 4];
    float s  = v.x + v.y + v.z + v.w;
    float sq = v.x * v.x + v.y * v.y + v.z * v.z + v.w * v.w;
    __shared__ float red[8];
    float s1 = warp_sum(s), s2 = warp_sum(sq);
    int warp = t >> 5, lane = t & 31;
    if (lane == 0) { red[warp] = s1; red[4 + warp] = s2; }
    __syncthreads();
    s1 = red[0] + red[1] + red[2] + red[3];
    s2 = red[4] + red[5] + red[6] + red[7];
    float mu = s1 * (1.0f / DMODEL);
    float var = s2 * (1.0f / DMODEL) - mu * mu;
    float inv = rsqrtf(var + 1e-5f);
    const float4 wv = *(const float4*)&w[t * 4];
    const float4 bv = *(const float4*)&b[t * 4];
    float4 o;
    o.x = (v.x - mu) * inv * wv.x + bv.x;
    o.y = (v.y - mu) * inv * wv.y + bv.y;
    o.z = (v.z - mu) * inv * wv.z + bv.z;
    o.w = (v.w - mu) * inv * wv.w + bv.w;
    return o;
}

__global__ void ln_kernel(const float* __restrict__ x,
                          const float* __restrict__ w,
                          const float* __restrict__ b,
                          float* __restrict__ y) {
    int row = blockIdx.x, t = threadIdx.x;
    float4 o = ln_row(x, w, b, row, t);
    *(float4*)&y[(size_t)row * DMODEL + t * 4] = o;
}

// LN fused with bf16 hi/lo split output
__global__ void ln_split_kernel(const float* __restrict__ x,
                                const float* __restrict__ w,
                                const float* __restrict__ b,
                                __nv_bfloat16* __restrict__ hi,
                                __nv_bfloat16* __restrict__ lo) {
    int row = blockIdx.x, t = threadIdx.x;
    float4 o = ln_row(x, w, b, row, t);
    __nv_bfloat16 hv[4], lv[4];
    split_store(o.x, &hv[0], &lv[0]);
    split_store(o.y, &hv[1], &lv[1]);
    split_store(o.z, &hv[2], &lv[2]);
    split_store(o.w, &hv[3], &lv[3]);
    int i = row * (DMODEL / 4) + t;
    ((uint64_t*)hi)[i] = *(uint64_t*)hv;
    ((uint64_t*)lo)[i] = *(uint64_t*)lv;
}

// ---------------- weight prep: all 24 matrices -> fused bf16 hi/lo ----------------
__global__ void weight_prep(const float* __restrict__ Wq, const float* __restrict__ Wk,
                            const float* __restrict__ Wv, const float* __restrict__ Wr,
                            const float* __restrict__ Wo, const float* __restrict__ Oc,
                            __nv_bfloat16* __restrict__ wh, __nv_bfloat16* __restrict__ wl) {
    int i = blockIdx.x * blockDim.x + threadIdx.x;   // float4 index
    const int per = MAT / 4;
    if (i >= 24 * per) return;
    int s = i / per;
    int off = i - s * per;
    const float* src;
    if (s < 16) {
        int l = s >> 2, t = s & 3;
        src = (t == 0 ? Wq : t == 1 ? Wk : t == 2 ? Wv : Wr) + (size_t)l * MAT;
    } else if (s < 20) {
        src = Wo + (size_t)(s - 16) * MAT;
    } else {
        src = Oc + (size_t)(s - 20) * MAT;
    }
    float4 v = ((const float4*)src)[off];
    __nv_bfloat16 hv[4], lv[4];
    split_store(v.x, &hv[0], &lv[0]);
    split_store(v.y, &hv[1], &lv[1]);
    split_store(v.z, &hv[2], &lv[2]);
    split_store(v.w, &hv[3], &lv[3]);
    ((uint64_t*)wh)[i] = *(uint64_t*)hv;
    ((uint64_t*)wl)[i] = *(uint64_t*)lv;
}

__global__ void mul_split_kernel(const float* __restrict__ a, const float* __restrict__ b,
                                 __nv_bfloat16* __restrict__ hi,
                                 __nv_bfloat16* __restrict__ lo, int n4) {
    int i = blockIdx.x * blockDim.x + threadIdx.x;
    if (i >= n4) return;
    float4 va = ((const float4*)a)[i];
    float4 vb = ((const float4*)b)[i];
    __nv_bfloat16 hv[4], lv[4];
    split_store(va.x * vb.x, &hv[0], &lv[0]);
    split_store(va.y * vb.y, &hv[1], &lv[1]);
    split_store(va.z * vb.z, &hv[2], &lv[2]);
    split_store(va.w * vb.w, &hv[3], &lv[3]);
    ((uint64_t*)hi)[i] = *(uint64_t*)hv;
    ((uint64_t*)lo)[i] = *(uint64_t*)lv;
}

// ---------------- shared GEMM mainloop machinery ----------------
#define GEMM_SMEM 65536
#define NCHUNK 24

__device__ __forceinline__ void gemm_stage(uint32_t smb, int tid, int m0, int n0, int c, int s,
                                           const __nv_bfloat16* ah, const __nv_bfloat16* al,
                                           const __nv_bfloat16* wh, const __nv_bfloat16* wl) {
    int sp = c >> 3, kc = (c & 7) * 64;
    const __nv_bfloat16* asrc = (sp == 2) ? al : ah;
    const __nv_bfloat16* wsrc = (sp == 1) ? wl : wh;
    int row = tid >> 1;
    int g0 = (tid & 1) * 4;
    const char* ga = (const char*)(asrc + (size_t)(m0 + row) * DMODEL + kc);
    const char* gw = (const char*)(wsrc + (size_t)(n0 + row) * DMODEL + kc);
    uint32_t sa = smb + s * 32768 + row * 128;
    uint32_t sb = sa + 16384;
#pragma unroll
    for (int j = 0; j < 4; j++) {
        int g = g0 + j;
        uint32_t so = (uint32_t)((g ^ (row & 7)) << 4);
        cp_async16(sa + so, ga + g * 16);
        cp_async16(sb + so, gw + g * 16);
    }
}

__device__ __forceinline__ void gemm_compute(uint32_t smb, int s, int wm, int wn, int lane,
                                             float acc[4][4][4]) {
    uint32_t Abase = smb + s * 32768;
    uint32_t Bbase = Abase + 16384;
#pragma unroll
    for (int k16 = 0; k16 < 4; k16++) {
        uint32_t a[4][4];
#pragma unroll
        for (int mi = 0; mi < 4; mi++) {
            int row = wm + mi * 16 + (lane & 15);
            int g = k16 * 2 + (lane >> 4);
            uint32_t addr = Abase + row * 128 + ((g ^ (row & 7)) << 4);
            ldsm4(a[mi][0], a[mi][1], a[mi][2], a[mi][3], addr);
        }
        uint32_t b[2][4];
#pragma unroll
        for (int nj = 0; nj < 2; nj++) {
            int row = wn + nj * 16 + ((lane >> 4) << 3) + (lane & 7);
            int g = k16 * 2 + ((lane >> 3) & 1);
            uint32_t addr = Bbase + row * 128 + ((g ^ (row & 7)) << 4);
            ldsm4(b[nj][0], b[nj][1], b[nj][2], b[nj][3], addr);
        }
#pragma unroll
        for (int mi = 0; mi < 4; mi++)
#pragma unroll
            for (int ni = 0; ni < 4; ni++)
                mma16816(acc[mi][ni], a[mi][0], a[mi][1], a[mi][2], a[mi][3],
                         b[ni >> 1][(ni & 1) * 2], b[ni >> 1][(ni & 1) * 2 + 1]);
    }
}

#define GEMM_MAINLOOP(AH, AL, WHp, WLp, M0, N0)                                  \
    gemm_stage(smb, tid, M0, N0, 0, 0, AH, AL, WHp, WLp);                        \
    asm volatile("cp.async.commit_group;");                                      \
    gemm_stage(smb, tid, M0, N0, 1, 1, AH, AL, WHp, WLp);                        \
    asm volatile("cp.async.commit_group;");                                      \
    for (int c = 0; c < NCHUNK; c++) {                                           \
        if (c < NCHUNK - 1) asm volatile("cp.async.wait_group 1;");              \
        else                asm volatile("cp.async.wait_group 0;");              \
        __syncthreads();                                                         \
        gemm_compute(smb, c & 1, wm, wn, lane, acc);                             \
        __syncthreads();                                                         \
        if (c + 2 < NCHUNK) {                                                    \
            gemm_stage(smb, tid, M0, N0, c + 2, c & 1, AH, AL, WHp, WLp);        \
            asm volatile("cp.async.commit_group;");                              \
        }                                                                        \
    }

// ---------------- standard GEMM (fp32 out, +bias +res) ----------------
template <bool BIAS, bool RES>
__global__ __launch_bounds__(256, 1)
void mma_gemm(const __nv_bfloat16* __restrict__ ah, const __nv_bfloat16* __restrict__ al,
              const __nv_bfloat16* __restrict__ wh, const __nv_bfloat16* __restrict__ wl,
              const float* __restrict__ bias, const float* __restrict__ res,
              float* __restrict__ C) {
    extern __shared__ char smem[];
    const uint32_t smb = smem_to_u32(smem);
    const int tid = threadIdx.x;
    const int wid = tid >> 5, lane = tid & 31;
    const int n0 = blockIdx.x * 128, m0 = blockIdx.y * 128;
    const int wm = (wid >> 2) * 64;
    const int wn = (wid & 3) * 32;

    float acc[4][4][4];
#pragma unroll
    for (int i = 0; i < 4; i++)
#pragma unroll
        for (int j = 0; j < 4; j++)
#pragma unroll
            for (int q = 0; q < 4; q++) acc[i][j][q] = 0.0f;

    GEMM_MAINLOOP(ah, al, wh, wl, m0, n0)

    const int lr = lane >> 2;
    const int lc = (lane & 3) * 2;
#pragma unroll
    for (int mi = 0; mi < 4; mi++) {
#pragma unroll
        for (int ni = 0; ni < 4; ni++) {
            int col = n0 + wn + ni * 8 + lc;
            float bx = 0.0f, by = 0.0f;
            if (BIAS) { bx = bias[col]; by = bias[col + 1]; }
            int row0 = m0 + wm + mi * 16 + lr;
            float v[4];
            v[0] = acc[mi][ni][0] + bx; v[1] = acc[mi][ni][1] + by;
            v[2] = acc[mi][ni][2] + bx; v[3] = acc[mi][ni][3] + by;
            size_t o0 = (size_t)row0 * DMODEL + col;
            size_t o1 = (size_t)(row0 + 8) * DMODEL + col;
            if (RES) {
                float2 r0 = *(const float2*)&res[o0];
                float2 r1 = *(const float2*)&res[o1];
                v[0] += r0.x; v[1] += r0.y; v[2] += r1.x; v[3] += r1.y;
            }
            *(float2*)&C[o0] = make_float2(v[0], v[1]);
            *(float2*)&C[o1] = make_float2(v[2], v[3]);
        }
    }
}

// ---------------- fused QKVR GEMM: N=2048 (4 types x 512) ----------------
__global__ __launch_bounds__(256, 1)
void qkvr_gemm(const __nv_bfloat16* __restrict__ ah, const __nv_bfloat16* __restrict__ al,
               const __nv_bfloat16* __restrict__ wh, const __nv_bfloat16* __restrict__ wl,
               const float* __restrict__ bq, const float* __restrict__ bk,
               const float* __restrict__ bv, const float* __restrict__ br,
               __nv_bfloat16* __restrict__ qh, __nv_bfloat16* __restrict__ ql,
               __nv_bfloat16* __restrict__ kh, __nv_bfloat16* __restrict__ kl,
               __nv_bfloat16* __restrict__ vhp, __nv_bfloat16* __restrict__ vlp,
               float* __restrict__ rr) {
    extern __shared__ char smem[];
    const uint32_t smb = smem_to_u32(smem);
    const int tid = threadIdx.x;
    const int wid = tid >> 5, lane = tid & 31;
    const int n0 = blockIdx.x * 128, m0 = blockIdx.y * 128;
    const int wm = (wid >> 2) * 64;
    const int wn = (wid & 3) * 32;

    float acc[4][4][4];
#pragma unroll
    for (int i = 0; i < 4; i++)
#pragma unroll
        for (int j = 0; j < 4; j++)
#pragma unroll
            for (int q = 0; q < 4; q++) acc[i][j][q] = 0.0f;

    GEMM_MAINLOOP(ah, al, wh, wl, m0, n0)

    const int type = blockIdx.x >> 2;
    const int ncol0 = (blockIdx.x & 3) * 128;   // col within 512
    const float* bias = (type == 0) ? bq : (type == 1) ? bk : (type == 2) ? bv : br;
    const float scale = (type == 0) ? 0.125f : 1.0f;
    __nv_bfloat16* Hi = (type == 0) ? qh : (type == 1) ? kh : vhp;
    __nv_bfloat16* Lo = (type == 0) ? ql : (type == 1) ? kl : vlp;

    const int lr = lane >> 2;
    const int lc = (lane & 3) * 2;
#pragma unroll
    for (int mi = 0; mi < 4; mi++) {
#pragma unroll
        for (int ni = 0; ni < 4; ni++) {
            int col = ncol0 + wn + ni * 8 + lc;
            float bx = bias[col], by = bias[col + 1];
            int row0 = m0 + wm + mi * 16 + lr;
            float v[4];
            v[0] = acc[mi][ni][0] + bx; v[1] = acc[mi][ni][1] + by;
            v[2] = acc[mi][ni][2] + bx; v[3] = acc[mi][ni][3] + by;
            size_t o0 = (size_t)row0 * DMODEL + col;
            size_t o1 = (size_t)(row0 + 8) * DMODEL + col;
            if (type == 3) {
                *(float2*)&rr[o0] = make_float2(v[0], v[1]);
                *(float2*)&rr[o1] = make_float2(v[2], v[3]);
            } else {
                __nv_bfloat16 hv[4], lv[4];
#pragma unroll
                for (int q = 0; q < 4; q++) {
                    float sv = v[q] * scale;
                    __nv_bfloat16 hh = __float2bfloat16(sv);
                    hv[q] = hh;
                    lv[q] = __float2bfloat16(sv - __bfloat162float(hh));
                }
                *(uint32_t*)&Hi[o0] = *(uint32_t*)&hv[0];
                *(uint32_t*)&Hi[o1] = *(uint32_t*)&hv[2];
                *(uint32_t*)&Lo[o0] = *(uint32_t*)&lv[0];
                *(uint32_t*)&Lo[o1] = *(uint32_t*)&lv[2];
            }
        }
    }
}

// ---------------- mma flash attention (bf16 3-split, fp32 softmax) ----------------
// 2-stage pipelined KV; V loaded row-major + ldmatrix.trans (no transpose copies).
// stage s (32KB): Kh@0 Kl@8192 Vh@16384 Vl@24576. masks at 65536 (2x64 ints).
#define AT_SMEM (65536 + 512)

__global__ __launch_bounds__(256, 1)
void attn_mma(const __nv_bfloat16* __restrict__ qh, const __nv_bfloat16* __restrict__ ql,
              const __nv_bfloat16* __restrict__ kh, const __nv_bfloat16* __restrict__ kl,
              const __nv_bfloat16* __restrict__ vh, const __nv_bfloat16* __restrict__ vl,
              const int* __restrict__ mask, float* __restrict__ vbar) {
    extern __shared__ char smem[];
    const uint32_t smb = smem_to_u32(smem);
    int* msk = (int*)(smem + 65536);
    const int tid = threadIdx.x;
    const int wid = tid >> 5, lane = tid & 31;
    const int b = blockIdx.z, h = blockIdx.y, q0 = blockIdx.x * 128;
    const int wm = wid * 16;
    const int lr = lane >> 2;
    const int lc = (lane & 3) * 2;

    // ---- stage Q (hi @0, lo @16384) into stage-0 region ----
    {
        int row = tid >> 1;
        int g0 = (tid & 1) * 4;
        size_t gofs = (size_t)(b * SEQ + q0 + row) * DMODEL + h * DHEAD;
        const char* gqh = (const char*)(qh + gofs);
        const char* gql = (const char*)(ql + gofs);
        uint32_t srow = smb + row * 128;
#pragma unroll
        for (int j = 0; j < 4; j++) {
            int g = g0 + j;
            uint32_t so = (uint32_t)((g ^ (row & 7)) << 4);
            cp_async16(srow + so, gqh + g * 16);
            cp_async16(srow + 16384 + so, gql + g * 16);
        }
    }
    asm volatile("cp.async.commit_group;");
    asm volatile("cp.async.wait_group 0;");
    __syncthreads();

    uint32_t Qh_[4][4], Ql_[4][4];
    {
        int row = wm + (lane & 15);
#pragma unroll
        for (int k16 = 0; k16 < 4; k16++) {
            int g = k16 * 2 + (lane >> 4);
            uint32_t so = (uint32_t)(row * 128 + ((g ^ (row & 7)) << 4));
            ldsm4(Qh_[k16][0], Qh_[k16][1], Qh_[k16][2], Qh_[k16][3], smb + so);
            ldsm4(Ql_[k16][0], Ql_[k16][1], Ql_[k16][2], Ql_[k16][3], smb + 16384 + so);
        }
    }
    __syncthreads();   // Q smem region reused for KV stages

    float Of[8][4];
#pragma unroll
    for (int i = 0; i < 8; i++)
#pragma unroll
        for (int q = 0; q < 4; q++) Of[i][q] = 0.0f;
    float m0r = -1e30f, m1r = -1e30f, l0 = 0.0f, l1 = 0.0f;

    // KV staging lambda: stage block jt into buffer s
    auto stage_kv = [&](int jt, int s) {
        int kv0 = jt * 64;
        int r = tid >> 2;
        int g0 = tid & 3;
        size_t gofs = (size_t)(b * SEQ + kv0 + r) * DMODEL + h * DHEAD;
        const char* pkh = (const char*)(kh + gofs);
        const char* pkl = (const char*)(kl + gofs);
        const char* pvh = (const char*)(vh + gofs);
        const char* pvl = (const char*)(vl + gofs);
        uint32_t base = smb + s * 32768 + r * 128;
#pragma unroll
        for (int t = 0; t < 2; t++) {
            int g = g0 + t * 4;
            uint32_t so = (uint32_t)((g ^ (r & 7)) << 4);
            cp_async16(base + so, pkh + g * 16);
            cp_async16(base + 8192 + so, pkl + g * 16);
            cp_async16(base + 16384 + so, pvh + g * 16);
            cp_async16(base + 24576 + so, pvl + g * 16);
        }
        if (tid < 64) msk[s * 64 + tid] = mask[b * SEQ + kv0 + tid];
    };

    stage_kv(0, 0);
    asm volatile("cp.async.commit_group;");

    for (int jt = 0; jt < SEQ / 64; jt++) {
        if (jt + 1 < SEQ / 64) {
            stage_kv(jt + 1, (jt + 1) & 1);
            asm volatile("cp.async.commit_group;");
            asm volatile("cp.async.wait_group 1;");
        } else {
            asm volatile("cp.async.wait_group 0;");
        }
        __syncthreads();
        const int s = jt & 1;
        const uint32_t Kbase = smb + s * 32768;
        const uint32_t Vbase = Kbase + 16384;
        const int* mskp = msk + s * 64;

        // ---- S = Qh*Kh + Qh*Kl + Ql*Kh ----
        float S[8][4];
#pragma unroll
        for (int i = 0; i < 8; i++)
#pragma unroll
            for (int q = 0; q < 4; q++) S[i][q] = 0.0f;
#pragma unroll
        for (int k16 = 0; k16 < 4; k16++) {
#pragma unroll
            for (int nj = 0; nj < 4; nj++) {
                int row = nj * 16 + ((lane >> 4) << 3) + (lane & 7);
                int g = k16 * 2 + ((lane >> 3) & 1);
                uint32_t so = (uint32_t)(row * 128 + ((g ^ (row & 7)) << 4));
                uint32_t bh0, bh1, bh2, bh3, bl0, bl1, bl2, bl3;
                ldsm4(bh0, bh1, bh2, bh3, Kbase + so);
                ldsm4(bl0, bl1, bl2, bl3, Kbase + 8192 + so);
                mma16816(S[2 * nj], Qh_[k16][0], Qh_[k16][1], Qh_[k16][2], Qh_[k16][3], bh0, bh1);
                mma16816(S[2 * nj], Qh_[k16][0], Qh_[k16][1], Qh_[k16][2], Qh_[k16][3], bl0, bl1);
                mma16816(S[2 * nj], Ql_[k16][0], Ql_[k16][1], Ql_[k16][2], Ql_[k16][3], bh0, bh1);
                mma16816(S[2 * nj + 1], Qh_[k16][0], Qh_[k16][1], Qh_[k16][2], Qh_[k16][3], bh2, bh3);
                mma16816(S[2 * nj + 1], Qh_[k16][0], Qh_[k16][1], Qh_[k16][2], Qh_[k16][3], bl2, bl3);
                mma16816(S[2 * nj + 1], Ql_[k16][0], Ql_[k16][1], Ql_[k16][2], Ql_[k16][3], bh2, bh3);
            }
        }
        // ---- mask + online softmax ----
#pragma unroll
        for (int ni = 0; ni < 8; ni++) {
            int j0 = ni * 8 + lc;
            if (mskp[j0] == 0)     { S[ni][0] = -1e10f; S[ni][2] = -1e10f; }
            if (mskp[j0 + 1] == 0) { S[ni][1] = -1e10f; S[ni][3] = -1e10f; }
        }
        float rmax0 = -1e30f, rmax1 = -1e30f;
#pragma unroll
        for (int ni = 0; ni < 8; ni++) {
            rmax0 = fmaxf(rmax0, fmaxf(S[ni][0], S[ni][1]));
            rmax1 = fmaxf(rmax1, fmaxf(S[ni][2], S[ni][3]));
        }
        rmax0 = fmaxf(rmax0, __shfl_xor_sync(0xffffffffu, rmax0, 1));
        rmax0 = fmaxf(rmax0, __shfl_xor_sync(0xffffffffu, rmax0, 2));
        rmax1 = fmaxf(rmax1, __shfl_xor_sync(0xffffffffu, rmax1, 1));
        rmax1 = fmaxf(rmax1, __shfl_xor_sync(0xffffffffu, rmax1, 2));
        float mn0 = fmaxf(m0r, rmax0), mn1 = fmaxf(m1r, rmax1);
        float corr0 = __expf(m0r - mn0), corr1 = __expf(m1r - mn1);
        m0r = mn0; m1r = mn1;
        float rs0 = 0.0f, rs1 = 0.0f;
#pragma unroll
        for (int ni = 0; ni < 8; ni++) {
            S[ni][0] = __expf(S[ni][0] - mn0); rs0 += S[ni][0];
            S[ni][1] = __expf(S[ni][1] - mn0); rs0 += S[ni][1];
            S[ni][2] = __expf(S[ni][2] - mn1); rs1 += S[ni][2];
            S[ni][3] = __expf(S[ni][3] - mn1); rs1 += S[ni][3];
        }
        rs0 += __shfl_xor_sync(0xffffffffu, rs0, 1);
        rs0 += __shfl_xor_sync(0xffffffffu, rs0, 2);
        rs1 += __shfl_xor_sync(0xffffffffu, rs1, 1);
        rs1 += __shfl_xor_sync(0xffffffffu, rs1, 2);
        l0 = l0 * corr0 + rs0;
        l1 = l1 * corr1 + rs1;
#pragma unroll
        for (int ni = 0; ni < 8; ni++) {
            Of[ni][0] *= corr0; Of[ni][1] *= corr0;
            Of[ni][2] *= corr1; Of[ni][3] *= corr1;
        }
        // ---- O += Ph*Vh + Ph*Vl + Pl*Vh (V via ldmatrix.trans) ----
#pragma unroll
        for (int k16 = 0; k16 < 4; k16++) {
            float2 f0 = make_float2(S[2 * k16][0], S[2 * k16][1]);
            float2 f1 = make_float2(S[2 * k16][2], S[2 * k16][3]);
            float2 f2 = make_float2(S[2 * k16 + 1][0], S[2 * k16 + 1][1]);
            float2 f3 = make_float2(S[2 * k16 + 1][2], S[2 * k16 + 1][3]);
            __nv_bfloat162 h0 = __float22bfloat162_rn(f0);
            __nv_bfloat162 h1 = __float22bfloat162_rn(f1);
            __nv_bfloat162 h2 = __float22bfloat162_rn(f2);
            __nv_bfloat162 h3 = __float22bfloat162_rn(f3);
            __nv_bfloat162 e0 = __float22bfloat162_rn(make_float2(f0.x - __low2float(h0), f0.y - __high2float(h0)));
            __nv_bfloat162 e1 = __float22bfloat162_rn(make_float2(f1.x - __low2float(h1), f1.y - __high2float(h1)));
            __nv_bfloat162 e2 = __float22bfloat162_rn(make_float2(f2.x - __low2float(h2), f2.y - __high2float(h2)));
            __nv_bfloat162 e3 = __float22bfloat162_rn(make_float2(f3.x - __low2float(h3), f3.y - __high2float(h3)));
            uint32_t ah0 = *(uint32_t*)&h0, ah1 = *(uint32_t*)&h1, ah2 = *(uint32_t*)&h2, ah3 = *(uint32_t*)&h3;
            uint32_t al0 = *(uint32_t*)&e0, al1 = *(uint32_t*)&e1, al2 = *(uint32_t*)&e2, al3 = *(uint32_t*)&e3;
            // trans address: quad = lane>>3 selects (kv half, d half)
            int quad = lane >> 3, lr8 = lane & 7;
            int vrow = k16 * 16 + (quad & 1) * 8 + lr8;
#pragma unroll
            for (int nj = 0; nj < 4; nj++) {
                int g = nj * 2 + (quad >> 1);
                uint32_t so = (uint32_t)(vrow * 128 + ((g ^ (vrow & 7)) << 4));
                uint32_t vh0, vh1, vh2, vh3, vl0, vl1, vl2, vl3;
                ldsm4t(vh0, vh1, vh2, vh3, Vbase + so);
                ldsm4t(vl0, vl1, vl2, vl3, Vbase + 8192 + so);
                mma16816(Of[2 * nj], ah0, ah1, ah2, ah3, vh0, vh1);
                mma16816(Of[2 * nj], ah0, ah1, ah2, ah3, vl0, vl1);
                mma16816(Of[2 * nj], al0, al1, al2, al3, vh0, vh1);
                mma16816(Of[2 * nj + 1], ah0, ah1, ah2, ah3, vh2, vh3);
                mma16816(Of[2 * nj + 1], ah0, ah1, ah2, ah3, vl2, vl3);
                mma16816(Of[2 * nj + 1], al0, al1, al2, al3, vh2, vh3);
            }
        }
        __syncthreads();
    }

    float inv0 = 1.0f / l0, inv1 = 1.0f / l1;
    int r0 = b * SEQ + q0 + wm + lr;
    int r1 = r0 + 8;
#pragma unroll
    for (int ni = 0; ni < 8; ni++) {
        int col = h * DHEAD + ni * 8 + lc;
        *(float2*)&vbar[(size_t)r0 * DMODEL + col] = make_float2(Of[ni][0] * inv0, Of[ni][1] * inv0);
        *(float2*)&vbar[(size_t)r1 * DMODEL + col] = make_float2(Of[ni][2] * inv1, Of[ni][3] * inv1);
    }
}

// ---------------- KAN inner fused with split ----------------
__device__ __forceinline__ float2 bspline01(float x) {
    const float h = 2.0f / 7.0f;
    const float i1 = 3.5f;
    const float i2 = 1.75f;
    const float i3 = 7.0f / 6.0f;
    float B0[5];
#pragma unroll
    for (int kk = 0; kk < 5; kk++) {
        float tk = -1.0f + kk * h;
        B0[kk] = (x >= tk && x < tk + h) ? 1.0f : 0.0f;
    }
    float B1[4];
#pragma unroll
    for (int kk = 0; kk < 4; kk++) {
        float tk = -1.0f + kk * h;
        B1[kk] = (x - tk) * i1 * B0[kk] + ((tk + 2.0f * h) - x) * i1 * B0[kk + 1];
    }
    float B2[3];
#pragma unroll
    for (int kk = 0; kk < 3; kk++) {
        float tk = -1.0f + kk * h;
        B2[kk] = (x - tk) * i2 * B1[kk] + ((tk + 3.0f * h) - x) * i2 * B1[kk + 1];
    }
    float2 r;
    {
        float tk = -1.0f;
        r.x = (x - tk) * i3 * B2[0] + ((tk + 4.0f * h) - x) * i3 * B2[1];
        tk = -1.0f + h;
        r.y = (x - tk) * i3 * B2[1] + ((tk + 4.0f * h) - x) * i3 * B2[2];
    }
    return r;
}

__global__ void kan_split_kernel(const float* __restrict__ z,
                                 const float* __restrict__ ic,
                                 __nv_bfloat16* __restrict__ hi,
                                 __nv_bfloat16* __restrict__ lo) {
    int i = blockIdx.x * blockDim.x + threadIdx.x;   // float4 index
    float4 zv = ((const float4*)z)[i];
    int d0 = (i * 4) & (DMODEL - 1);
    __nv_bfloat16 hv[4], lv[4];
    float zz[4] = {zv.x, zv.y, zv.z, zv.w};
#pragma unroll
    for (int q = 0; q < 4; q++) {
        float x = tanhf(zz[q]);
        float2 bs = bspline01(x);
        int d = d0 + q;
        float val = bs.x * ic[d * 5 + 0] + bs.y * ic[d * 5 + 1];
        split_store(val, &hv[q], &lv[q]);
    }
    ((uint64_t*)hi)[i] = *(uint64_t*)hv;
    ((uint64_t*)lo)[i] = *(uint64_t*)lv;
}

// ---------------- host ----------------
extern "C" void kernel_launch(void* const* d_in, const int* in_sizes, int n_in,
                              void* d_out, int out_size) {
    const float* src    = (const float*)d_in[0];
    const float* ln1_w  = (const float*)d_in[1];
    const float* ln1_b  = (const float*)d_in[2];
    const float* ln2_w  = (const float*)d_in[3];
    const float* ln2_b  = (const float*)d_in[4];
    const float* ln3_w  = (const float*)d_in[5];
    const float* ln3_b  = (const float*)d_in[6];
    const float* Wq_w   = (const float*)d_in[7];
    const float* Wq_b   = (const float*)d_in[8];
    const float* Wk_w   = (const float*)d_in[9];
    const float* Wk_b   = (const float*)d_in[10];
    const float* Wv_w   = (const float*)d_in[11];
    const float* Wv_b   = (const float*)d_in[12];
    const float* Wr_w   = (const float*)d_in[13];
    const float* Wr_b   = (const float*)d_in[14];
    const float* Wo_w   = (const float*)d_in[15];
    const float* Wo_b   = (const float*)d_in[16];
    const float* inner_c= (const float*)d_in[17];
    const float* outer_c= (const float*)d_in[18];
    const int*   mask   = (const int*)d_in[19];
    float* out = (float*)d_out;

    float *z, *r, *vb;
    __nv_bfloat16 *wh, *wl, *ah, *al, *qh, *ql, *kh, *kl, *vh, *vl;
    cudaGetSymbolAddress((void**)&z, g_z);
    cudaGetSymbolAddress((void**)&r, g_r);
    cudaGetSymbolAddress((void**)&vb, g_vb);
    cudaGetSymbolAddress((void**)&wh, g_wh);
    cudaGetSymbolAddress((void**)&wl, g_wl);
    cudaGetSymbolAddress((void**)&ah, g_ah);
    cudaGetSymbolAddress((void**)&al, g_al);
    cudaGetSymbolAddress((void**)&qh, g_qh);
    cudaGetSymbolAddress((void**)&ql, g_ql);
    cudaGetSymbolAddress((void**)&kh, g_kh);
    cudaGetSymbolAddress((void**)&kl, g_kl);
    cudaGetSymbolAddress((void**)&vh, g_vh);
    cudaGetSymbolAddress((void**)&vl, g_vl);

    cudaFuncSetAttribute(attn_mma, cudaFuncAttributeMaxDynamicSharedMemorySize, AT_SMEM);
    cudaFuncSetAttribute(qkvr_gemm, cudaFuncAttributeMaxDynamicSharedMemorySize, GEMM_SMEM);
    cudaFuncSetAttribute(mma_gemm<true, true>, cudaFuncAttributeMaxDynamicSharedMemorySize, GEMM_SMEM);
    cudaFuncSetAttribute(mma_gemm<false, true>, cudaFuncAttributeMaxDynamicSharedMemorySize, GEMM_SMEM);

    // weights -> fused bf16 hi/lo, one launch
    {
        int n4 = 24 * MAT / 4;
        weight_prep<<<(n4 + 255) / 256, 256>>>(Wq_w, Wk_w, Wv_w, Wr_w, Wo_w, outer_c, wh, wl);
    }

    cudaMemcpyAsync(out, src, (size_t)ROWS * DMODEL * sizeof(float),
                    cudaMemcpyDeviceToDevice, 0);

    const int an4 = ROWS * DMODEL / 4;
    const int ablocks = (an4 + 255) / 256;
    dim3 ggrid(DMODEL / 128, ROWS / 128);
    dim3 qgrid(2048 / 128, ROWS / 128);

    for (int l = 0; l < NLAYER; l++) {
        const __nv_bfloat16* whQ = wh + (size_t)(4 * l) * MAT;
        const __nv_bfloat16* wlQ = wl + (size_t)(4 * l) * MAT;
        const __nv_bfloat16* whO = wh + (size_t)(16 + l) * MAT;
        const __nv_bfloat16* wlO = wl + (size_t)(16 + l) * MAT;
        const __nv_bfloat16* whC = wh + (size_t)(20 + l) * MAT;
        const __nv_bfloat16* wlC = wl + (size_t)(20 + l) * MAT;
        // --- attention block ---
        ln_split_kernel<<<ROWS, 128>>>(out, ln1_w + l * DMODEL, ln1_b + l * DMODEL, ah, al);
        qkvr_gemm<<<qgrid, 256, GEMM_SMEM>>>(ah, al, whQ, wlQ,
                                             Wq_b + l * DMODEL, Wk_b + l * DMODEL,
                                             Wv_b + l * DMODEL, Wr_b + l * DMODEL,
                                             qh, ql, kh, kl, vh, vl, r);
        attn_mma<<<dim3(SEQ / 128, NHEAD, BSZ), 256, AT_SMEM>>>(qh, ql, kh, kl, vh, vl, mask, vb);
        mul_split_kernel<<<ablocks, 256>>>(vb, r, ah, al, an4);
        mma_gemm<true, true><<<ggrid, 256, GEMM_SMEM>>>(ah, al, whO, wlO, Wo_b + l * DMODEL, out, out);
        // --- KAN block ---
        ln_kernel<<<ROWS, 128>>>(out, ln2_w + l * DMODEL, ln2_b + l * DMODEL, z);
        kan_split_kernel<<<ablocks, 256>>>(z, inner_c + l * DMODEL * 5, ah, al);
        mma_gemm<false, true><<<ggrid, 256, GEMM_SMEM>>>(ah, al, whC, wlC, nullptr, out, out);
        ln_kernel<<<ROWS, 128>>>(out, ln3_w + l * DMODEL, ln3_b + l * DMODEL, out);
    }
}

// round 9
// speedup vs baseline: 2.7737x; 1.1796x over previous
#include <cuda_runtime.h>
#include <cuda_bf16.h>
#include <math.h>
#include <stdint.h>

// Problem constants
#define BSZ 4
#define SEQ 1024
#define DMODEL 512
#define NHEAD 8
#define DHEAD 64
#define NLAYER 4
#define ROWS (BSZ * SEQ)          // 4096
#define MAT (DMODEL * DMODEL)     // 262144

// ---------------- scratch (device globals; no allocation) ----------------
__device__ float g_r[ROWS * DMODEL];
// bf16 split buffers. Weight layout: QKVR fused per layer at (4l+t)*MAT,
// Wo at (16+l)*MAT, outer at (20+l)*MAT.
__device__ __nv_bfloat16 g_wh[24 * MAT];
__device__ __nv_bfloat16 g_wl[24 * MAT];
__device__ __nv_bfloat16 g_ah[ROWS * DMODEL];
__device__ __nv_bfloat16 g_al[ROWS * DMODEL];
// attention operand buffers (bf16 hi/lo), layout [b*SEQ+s][h*64+d]
__device__ __nv_bfloat16 g_qh[ROWS * DMODEL];
__device__ __nv_bfloat16 g_ql[ROWS * DMODEL];
__device__ __nv_bfloat16 g_kh[ROWS * DMODEL];
__device__ __nv_bfloat16 g_kl[ROWS * DMODEL];
__device__ __nv_bfloat16 g_vh[ROWS * DMODEL];
__device__ __nv_bfloat16 g_vl[ROWS * DMODEL];

// ---------------- PTX helpers (sm_80+ features only) ----------------
__device__ __forceinline__ uint32_t smem_to_u32(const void* p) {
    uint32_t a;
    asm("{ .reg .u64 t; cvta.to.shared.u64 t, %1; cvt.u32.u64 %0, t; }" : "=r"(a) : "l"(p));
    return a;
}
__device__ __forceinline__ void cp_async16(uint32_t dst, const void* src) {
    asm volatile("cp.async.cg.shared.global [%0], [%1], 16;" :: "r"(dst), "l"(src));
}
__device__ __forceinline__ void ldsm4(uint32_t& r0, uint32_t& r1, uint32_t& r2, uint32_t& r3,
                                      uint32_t a) {
    asm volatile("ldmatrix.sync.aligned.m8n8.x4.shared.b16 {%0,%1,%2,%3}, [%4];"
                 : "=r"(r0), "=r"(r1), "=r"(r2), "=r"(r3) : "r"(a));
}
__device__ __forceinline__ void ldsm4t(uint32_t& r0, uint32_t& r1, uint32_t& r2, uint32_t& r3,
                                       uint32_t a) {
    asm volatile("ldmatrix.sync.aligned.m8n8.x4.trans.shared.b16 {%0,%1,%2,%3}, [%4];"
                 : "=r"(r0), "=r"(r1), "=r"(r2), "=r"(r3) : "r"(a));
}
__device__ __forceinline__ void mma16816(float* c, uint32_t a0, uint32_t a1, uint32_t a2,
                                         uint32_t a3, uint32_t b0, uint32_t b1) {
    asm volatile(
        "mma.sync.aligned.m16n8k16.row.col.f32.bf16.bf16.f32 "
        "{%0,%1,%2,%3}, {%4,%5,%6,%7}, {%8,%9}, {%0,%1,%2,%3};"
        : "+f"(c[0]), "+f"(c[1]), "+f"(c[2]), "+f"(c[3])
        : "r"(a0), "r"(a1), "r"(a2), "r"(a3), "r"(b0), "r"(b1));
}

__device__ __forceinline__ void split_store(float v, __nv_bfloat16* hi, __nv_bfloat16* lo) {
    __nv_bfloat16 h = __float2bfloat16(v);
    *hi = h;
    *lo = __float2bfloat16(v - __bfloat162float(h));
}

// ---------------- LayerNorm helpers ----------------
__inline__ __device__ float warp_sum(float v) {
#pragma unroll
    for (int o = 16; o; o >>= 1) v += __shfl_xor_sync(0xffffffffu, v, o);
    return v;
}

__device__ __forceinline__ float4 ln_row(const float* __restrict__ x,
                                         const float* __restrict__ w,
                                         const float* __restrict__ b,
                                         int row, int t) {
    const float4 v = *(const float4*)&x[(size_t)row * DMODEL + t * 4];
    float s  = v.x + v.y + v.z + v.w;
    float sq = v.x * v.x + v.y * v.y + v.z * v.z + v.w * v.w;
    __shared__ float red[8];
    float s1 = warp_sum(s), s2 = warp_sum(sq);
    int warp = t >> 5, lane = t & 31;
    if (lane == 0) { red[warp] = s1; red[4 + warp] = s2; }
    __syncthreads();
    s1 = red[0] + red[1] + red[2] + red[3];
    s2 = red[4] + red[5] + red[6] + red[7];
    float mu = s1 * (1.0f / DMODEL);
    float var = s2 * (1.0f / DMODEL) - mu * mu;
    float inv = rsqrtf(var + 1e-5f);
    const float4 wv = *(const float4*)&w[t * 4];
    const float4 bv = *(const float4*)&b[t * 4];
    float4 o;
    o.x = (v.x - mu) * inv * wv.x + bv.x;
    o.y = (v.y - mu) * inv * wv.y + bv.y;
    o.z = (v.z - mu) * inv * wv.z + bv.z;
    o.w = (v.w - mu) * inv * wv.w + bv.w;
    return o;
}

__global__ void ln_kernel(const float* __restrict__ x,
                          const float* __restrict__ w,
                          const float* __restrict__ b,
                          float* __restrict__ y) {
    int row = blockIdx.x, t = threadIdx.x;
    float4 o = ln_row(x, w, b, row, t);
    *(float4*)&y[(size_t)row * DMODEL + t * 4] = o;
}

// LN fused with bf16 hi/lo split output
__global__ void ln_split_kernel(const float* __restrict__ x,
                                const float* __restrict__ w,
                                const float* __restrict__ b,
                                __nv_bfloat16* __restrict__ hi,
                                __nv_bfloat16* __restrict__ lo) {
    int row = blockIdx.x, t = threadIdx.x;
    float4 o = ln_row(x, w, b, row, t);
    __nv_bfloat16 hv[4], lv[4];
    split_store(o.x, &hv[0], &lv[0]);
    split_store(o.y, &hv[1], &lv[1]);
    split_store(o.z, &hv[2], &lv[2]);
    split_store(o.w, &hv[3], &lv[3]);
    int i = row * (DMODEL / 4) + t;
    ((uint64_t*)hi)[i] = *(uint64_t*)hv;
    ((uint64_t*)lo)[i] = *(uint64_t*)lv;
}

// LN3 then LN1(next layer) fused: y = LN3(x); hi/lo = split(LN1(y)).
__global__ void ln3_ln1_kernel(const float* __restrict__ x,
                               const float* __restrict__ w3, const float* __restrict__ b3,
                               const float* __restrict__ w1, const float* __restrict__ b1,
                               float* __restrict__ y,
                               __nv_bfloat16* __restrict__ hi,
                               __nv_bfloat16* __restrict__ lo) {
    int row = blockIdx.x, t = threadIdx.x;
    int warp = t >> 5, lane = t & 31;
    __shared__ float red[8];
    // pass 1: LN3
    const float4 v = *(const float4*)&x[(size_t)row * DMODEL + t * 4];
    float s = v.x + v.y + v.z + v.w;
    float sq = v.x * v.x + v.y * v.y + v.z * v.z + v.w * v.w;
    float s1 = warp_sum(s), s2 = warp_sum(sq);
    if (lane == 0) { red[warp] = s1; red[4 + warp] = s2; }
    __syncthreads();
    s1 = red[0] + red[1] + red[2] + red[3];
    s2 = red[4] + red[5] + red[6] + red[7];
    float mu = s1 * (1.0f / DMODEL);
    float var = s2 * (1.0f / DMODEL) - mu * mu;
    float inv = rsqrtf(var + 1e-5f);
    const float4 w3v = *(const float4*)&w3[t * 4];
    const float4 b3v = *(const float4*)&b3[t * 4];
    float4 o3;
    o3.x = (v.x - mu) * inv * w3v.x + b3v.x;
    o3.y = (v.y - mu) * inv * w3v.y + b3v.y;
    o3.z = (v.z - mu) * inv * w3v.z + b3v.z;
    o3.w = (v.w - mu) * inv * w3v.w + b3v.w;
    *(float4*)&y[(size_t)row * DMODEL + t * 4] = o3;
    __syncthreads();
    // pass 2: LN1 on o3
    s = o3.x + o3.y + o3.z + o3.w;
    sq = o3.x * o3.x + o3.y * o3.y + o3.z * o3.z + o3.w * o3.w;
    s1 = warp_sum(s); s2 = warp_sum(sq);
    if (lane == 0) { red[warp] = s1; red[4 + warp] = s2; }
    __syncthreads();
    s1 = red[0] + red[1] + red[2] + red[3];
    s2 = red[4] + red[5] + red[6] + red[7];
    mu = s1 * (1.0f / DMODEL);
    var = s2 * (1.0f / DMODEL) - mu * mu;
    inv = rsqrtf(var + 1e-5f);
    const float4 w1v = *(const float4*)&w1[t * 4];
    const float4 b1v = *(const float4*)&b1[t * 4];
    float o1[4];
    o1[0] = (o3.x - mu) * inv * w1v.x + b1v.x;
    o1[1] = (o3.y - mu) * inv * w1v.y + b1v.y;
    o1[2] = (o3.z - mu) * inv * w1v.z + b1v.z;
    o1[3] = (o3.w - mu) * inv * w1v.w + b1v.w;
    __nv_bfloat16 hv[4], lv[4];
#pragma unroll
    for (int q = 0; q < 4; q++) split_store(o1[q], &hv[q], &lv[q]);
    int i = row * (DMODEL / 4) + t;
    ((uint64_t*)hi)[i] = *(uint64_t*)hv;
    ((uint64_t*)lo)[i] = *(uint64_t*)lv;
}

// ---------------- weight prep: all 24 matrices -> fused bf16 hi/lo ----------------
__global__ void weight_prep(const float* __restrict__ Wq, const float* __restrict__ Wk,
                            const float* __restrict__ Wv, const float* __restrict__ Wr,
                            const float* __restrict__ Wo, const float* __restrict__ Oc,
                            __nv_bfloat16* __restrict__ wh, __nv_bfloat16* __restrict__ wl) {
    int i = blockIdx.x * blockDim.x + threadIdx.x;   // float4 index
    const int per = MAT / 4;
    if (i >= 24 * per) return;
    int s = i / per;
    int off = i - s * per;
    const float* src;
    if (s < 16) {
        int l = s >> 2, t = s & 3;
        src = (t == 0 ? Wq : t == 1 ? Wk : t == 2 ? Wv : Wr) + (size_t)l * MAT;
    } else if (s < 20) {
        src = Wo + (size_t)(s - 16) * MAT;
    } else {
        src = Oc + (size_t)(s - 20) * MAT;
    }
    float4 v = ((const float4*)src)[off];
    __nv_bfloat16 hv[4], lv[4];
    split_store(v.x, &hv[0], &lv[0]);
    split_store(v.y, &hv[1], &lv[1]);
    split_store(v.z, &hv[2], &lv[2]);
    split_store(v.w, &hv[3], &lv[3]);
    ((uint64_t*)wh)[i] = *(uint64_t*)hv;
    ((uint64_t*)wl)[i] = *(uint64_t*)lv;
}

// ---------------- shared GEMM mainloop (tile-once 3-split) ----------------
// 8 K-chunks of 64. Per stage (64KB): Ah@0 Al@16384 Wh@32768 Wl@49152.
// Double buffered -> 128KB smem.
#define GEMM_SMEM 131072
#define NCHUNK 8

__device__ __forceinline__ void gemm_stage(uint32_t smb, int tid, int m0, int n0, int kc, int s,
                                           const __nv_bfloat16* ah, const __nv_bfloat16* al,
                                           const __nv_bfloat16* wh, const __nv_bfloat16* wl) {
    int row = tid >> 1;
    int g0 = (tid & 1) * 4;
    const char* pa0 = (const char*)(ah + (size_t)(m0 + row) * DMODEL + kc);
    const char* pa1 = (const char*)(al + (size_t)(m0 + row) * DMODEL + kc);
    const char* pb0 = (const char*)(wh + (size_t)(n0 + row) * DMODEL + kc);
    const char* pb1 = (const char*)(wl + (size_t)(n0 + row) * DMODEL + kc);
    uint32_t base = smb + s * 65536 + row * 128;
#pragma unroll
    for (int j = 0; j < 4; j++) {
        int g = g0 + j;
        uint32_t so = (uint32_t)((g ^ (row & 7)) << 4);
        cp_async16(base + so, pa0 + g * 16);
        cp_async16(base + 16384 + so, pa1 + g * 16);
        cp_async16(base + 32768 + so, pb0 + g * 16);
        cp_async16(base + 49152 + so, pb1 + g * 16);
    }
}

__device__ __forceinline__ void gemm_compute(uint32_t smb, int s, int wm, int wn, int lane,
                                             float acc[4][4][4]) {
    uint32_t A0 = smb + s * 65536;
    uint32_t A1 = A0 + 16384;
    uint32_t B0 = A0 + 32768;
    uint32_t B1 = A0 + 49152;
#pragma unroll
    for (int k16 = 0; k16 < 4; k16++) {
        uint32_t aH[4][4], aL[4][4];
#pragma unroll
        for (int mi = 0; mi < 4; mi++) {
            int row = wm + mi * 16 + (lane & 15);
            int g = k16 * 2 + (lane >> 4);
            uint32_t so = (uint32_t)(row * 128 + ((g ^ (row & 7)) << 4));
            ldsm4(aH[mi][0], aH[mi][1], aH[mi][2], aH[mi][3], A0 + so);
            ldsm4(aL[mi][0], aL[mi][1], aL[mi][2], aL[mi][3], A1 + so);
        }
        uint32_t bH[2][4], bL[2][4];
#pragma unroll
        for (int nj = 0; nj < 2; nj++) {
            int row = wn + nj * 16 + ((lane >> 4) << 3) + (lane & 7);
            int g = k16 * 2 + ((lane >> 3) & 1);
            uint32_t so = (uint32_t)(row * 128 + ((g ^ (row & 7)) << 4));
            ldsm4(bH[nj][0], bH[nj][1], bH[nj][2], bH[nj][3], B0 + so);
            ldsm4(bL[nj][0], bL[nj][1], bL[nj][2], bL[nj][3], B1 + so);
        }
#pragma unroll
        for (int mi = 0; mi < 4; mi++)
#pragma unroll
            for (int ni = 0; ni < 4; ni++) {
                uint32_t h0 = bH[ni >> 1][(ni & 1) * 2], h1 = bH[ni >> 1][(ni & 1) * 2 + 1];
                uint32_t l0 = bL[ni >> 1][(ni & 1) * 2], l1 = bL[ni >> 1][(ni & 1) * 2 + 1];
                mma16816(acc[mi][ni], aH[mi][0], aH[mi][1], aH[mi][2], aH[mi][3], h0, h1);
                mma16816(acc[mi][ni], aH[mi][0], aH[mi][1], aH[mi][2], aH[mi][3], l0, l1);
                mma16816(acc[mi][ni], aL[mi][0], aL[mi][1], aL[mi][2], aL[mi][3], h0, h1);
            }
    }
}

#define GEMM_MAINLOOP(AH, AL, WHp, WLp, M0, N0)                                      \
    gemm_stage(smb, tid, M0, N0, 0, 0, AH, AL, WHp, WLp);                            \
    asm volatile("cp.async.commit_group;");                                          \
    gemm_stage(smb, tid, M0, N0, 64, 1, AH, AL, WHp, WLp);                           \
    asm volatile("cp.async.commit_group;");                                          \
    for (int c = 0; c < NCHUNK; c++) {                                               \
        if (c < NCHUNK - 1) asm volatile("cp.async.wait_group 1;");                  \
        else                asm volatile("cp.async.wait_group 0;");                  \
        __syncthreads();                                                             \
        gemm_compute(smb, c & 1, wm, wn, lane, acc);                                 \
        __syncthreads();                                                             \
        if (c + 2 < NCHUNK) {                                                        \
            gemm_stage(smb, tid, M0, N0, (c + 2) * 64, c & 1, AH, AL, WHp, WLp);     \
            asm volatile("cp.async.commit_group;");                                  \
        }                                                                            \
    }

// ---------------- standard GEMM (fp32 out, +bias +res) ----------------
template <bool BIAS, bool RES>
__global__ __launch_bounds__(256, 1)
void mma_gemm(const __nv_bfloat16* __restrict__ ah, const __nv_bfloat16* __restrict__ al,
              const __nv_bfloat16* __restrict__ wh, const __nv_bfloat16* __restrict__ wl,
              const float* __restrict__ bias, const float* __restrict__ res,
              float* __restrict__ C) {
    extern __shared__ char smem[];
    const uint32_t smb = smem_to_u32(smem);
    const int tid = threadIdx.x;
    const int wid = tid >> 5, lane = tid & 31;
    const int n0 = blockIdx.x * 128, m0 = blockIdx.y * 128;
    const int wm = (wid >> 2) * 64;
    const int wn = (wid & 3) * 32;

    float acc[4][4][4];
#pragma unroll
    for (int i = 0; i < 4; i++)
#pragma unroll
        for (int j = 0; j < 4; j++)
#pragma unroll
            for (int q = 0; q < 4; q++) acc[i][j][q] = 0.0f;

    GEMM_MAINLOOP(ah, al, wh, wl, m0, n0)

    const int lr = lane >> 2;
    const int lc = (lane & 3) * 2;
#pragma unroll
    for (int mi = 0; mi < 4; mi++) {
#pragma unroll
        for (int ni = 0; ni < 4; ni++) {
            int col = n0 + wn + ni * 8 + lc;
            float bx = 0.0f, by = 0.0f;
            if (BIAS) { bx = bias[col]; by = bias[col + 1]; }
            int row0 = m0 + wm + mi * 16 + lr;
            float v[4];
            v[0] = acc[mi][ni][0] + bx; v[1] = acc[mi][ni][1] + by;
            v[2] = acc[mi][ni][2] + bx; v[3] = acc[mi][ni][3] + by;
            size_t o0 = (size_t)row0 * DMODEL + col;
            size_t o1 = (size_t)(row0 + 8) * DMODEL + col;
            if (RES) {
                float2 r0 = *(const float2*)&res[o0];
                float2 r1 = *(const float2*)&res[o1];
                v[0] += r0.x; v[1] += r0.y; v[2] += r1.x; v[3] += r1.y;
            }
            *(float2*)&C[o0] = make_float2(v[0], v[1]);
            *(float2*)&C[o1] = make_float2(v[2], v[3]);
        }
    }
}

// ---------------- fused QKVR GEMM: N=2048 (4 types x 512) ----------------
__global__ __launch_bounds__(256, 1)
void qkvr_gemm(const __nv_bfloat16* __restrict__ ah, const __nv_bfloat16* __restrict__ al,
               const __nv_bfloat16* __restrict__ wh, const __nv_bfloat16* __restrict__ wl,
               const float* __restrict__ bq, const float* __restrict__ bk,
               const float* __restrict__ bv, const float* __restrict__ br,
               __nv_bfloat16* __restrict__ qh, __nv_bfloat16* __restrict__ ql,
               __nv_bfloat16* __restrict__ kh, __nv_bfloat16* __restrict__ kl,
               __nv_bfloat16* __restrict__ vhp, __nv_bfloat16* __restrict__ vlp,
               float* __restrict__ rr) {
    extern __shared__ char smem[];
    const uint32_t smb = smem_to_u32(smem);
    const int tid = threadIdx.x;
    const int wid = tid >> 5, lane = tid & 31;
    const int n0 = blockIdx.x * 128, m0 = blockIdx.y * 128;
    const int wm = (wid >> 2) * 64;
    const int wn = (wid & 3) * 32;

    float acc[4][4][4];
#pragma unroll
    for (int i = 0; i < 4; i++)
#pragma unroll
        for (int j = 0; j < 4; j++)
#pragma unroll
            for (int q = 0; q < 4; q++) acc[i][j][q] = 0.0f;

    GEMM_MAINLOOP(ah, al, wh, wl, m0, n0)

    const int type = blockIdx.x >> 2;
    const int ncol0 = (blockIdx.x & 3) * 128;   // col within 512
    const float* bias = (type == 0) ? bq : (type == 1) ? bk : (type == 2) ? bv : br;
    const float scale = (type == 0) ? 0.125f : 1.0f;
    __nv_bfloat16* Hi = (type == 0) ? qh : (type == 1) ? kh : vhp;
    __nv_bfloat16* Lo = (type == 0) ? ql : (type == 1) ? kl : vlp;

    const int lr = lane >> 2;
    const int lc = (lane & 3) * 2;
#pragma unroll
    for (int mi = 0; mi < 4; mi++) {
#pragma unroll
        for (int ni = 0; ni < 4; ni++) {
            int col = ncol0 + wn + ni * 8 + lc;
            float bx = bias[col], by = bias[col + 1];
            int row0 = m0 + wm + mi * 16 + lr;
            float v[4];
            v[0] = acc[mi][ni][0] + bx; v[1] = acc[mi][ni][1] + by;
            v[2] = acc[mi][ni][2] + bx; v[3] = acc[mi][ni][3] + by;
            size_t o0 = (size_t)row0 * DMODEL + col;
            size_t o1 = (size_t)(row0 + 8) * DMODEL + col;
            if (type == 3) {
                *(float2*)&rr[o0] = make_float2(v[0], v[1]);
                *(float2*)&rr[o1] = make_float2(v[2], v[3]);
            } else {
                __nv_bfloat16 hv[4], lv[4];
#pragma unroll
                for (int q = 0; q < 4; q++) {
                    float sv = v[q] * scale;
                    __nv_bfloat16 hh = __float2bfloat16(sv);
                    hv[q] = hh;
                    lv[q] = __float2bfloat16(sv - __bfloat162float(hh));
                }
                *(uint32_t*)&Hi[o0] = *(uint32_t*)&hv[0];
                *(uint32_t*)&Hi[o1] = *(uint32_t*)&hv[2];
                *(uint32_t*)&Lo[o0] = *(uint32_t*)&lv[0];
                *(uint32_t*)&Lo[o1] = *(uint32_t*)&lv[2];
            }
        }
    }
}

// ---------------- mma flash attention (bf16 3-split, fp32 softmax) ----------------
// 2-stage pipelined KV; V row-major + ldmatrix.trans. Epilogue fuses *R + bf16 split.
#define AT_SMEM (65536 + 512)

__global__ __launch_bounds__(256, 1)
void attn_mma(const __nv_bfloat16* __restrict__ qh, const __nv_bfloat16* __restrict__ ql,
              const __nv_bfloat16* __restrict__ kh, const __nv_bfloat16* __restrict__ kl,
              const __nv_bfloat16* __restrict__ vh, const __nv_bfloat16* __restrict__ vl,
              const int* __restrict__ mask, const float* __restrict__ rmul,
              __nv_bfloat16* __restrict__ oh, __nv_bfloat16* __restrict__ ol) {
    extern __shared__ char smem[];
    const uint32_t smb = smem_to_u32(smem);
    int* msk = (int*)(smem + 65536);
    const int tid = threadIdx.x;
    const int wid = tid >> 5, lane = tid & 31;
    const int b = blockIdx.z, h = blockIdx.y, q0 = blockIdx.x * 128;
    const int wm = wid * 16;
    const int lr = lane >> 2;
    const int lc = (lane & 3) * 2;

    // ---- stage Q (hi @0, lo @16384) into stage-0 region ----
    {
        int row = tid >> 1;
        int g0 = (tid & 1) * 4;
        size_t gofs = (size_t)(b * SEQ + q0 + row) * DMODEL + h * DHEAD;
        const char* gqh = (const char*)(qh + gofs);
        const char* gql = (const char*)(ql + gofs);
        uint32_t srow = smb + row * 128;
#pragma unroll
        for (int j = 0; j < 4; j++) {
            int g = g0 + j;
            uint32_t so = (uint32_t)((g ^ (row & 7)) << 4);
            cp_async16(srow + so, gqh + g * 16);
            cp_async16(srow + 16384 + so, gql + g * 16);
        }
    }
    asm volatile("cp.async.commit_group;");
    asm volatile("cp.async.wait_group 0;");
    __syncthreads();

    uint32_t Qh_[4][4], Ql_[4][4];
    {
        int row = wm + (lane & 15);
#pragma unroll
        for (int k16 = 0; k16 < 4; k16++) {
            int g = k16 * 2 + (lane >> 4);
            uint32_t so = (uint32_t)(row * 128 + ((g ^ (row & 7)) << 4));
            ldsm4(Qh_[k16][0], Qh_[k16][1], Qh_[k16][2], Qh_[k16][3], smb + so);
            ldsm4(Ql_[k16][0], Ql_[k16][1], Ql_[k16][2], Ql_[k16][3], smb + 16384 + so);
        }
    }
    __syncthreads();   // Q smem region reused for KV stages

    float Of[8][4];
#pragma unroll
    for (int i = 0; i < 8; i++)
#pragma unroll
        for (int q = 0; q < 4; q++) Of[i][q] = 0.0f;
    float m0r = -1e30f, m1r = -1e30f, l0 = 0.0f, l1 = 0.0f;

    auto stage_kv = [&](int jt, int s) {
        int kv0 = jt * 64;
        int r = tid >> 2;
        int g0 = tid & 3;
        size_t gofs = (size_t)(b * SEQ + kv0 + r) * DMODEL + h * DHEAD;
        const char* pkh = (const char*)(kh + gofs);
        const char* pkl = (const char*)(kl + gofs);
        const char* pvh = (const char*)(vh + gofs);
        const char* pvl = (const char*)(vl + gofs);
        uint32_t base = smb + s * 32768 + r * 128;
#pragma unroll
        for (int t = 0; t < 2; t++) {
            int g = g0 + t * 4;
            uint32_t so = (uint32_t)((g ^ (r & 7)) << 4);
            cp_async16(base + so, pkh + g * 16);
            cp_async16(base + 8192 + so, pkl + g * 16);
            cp_async16(base + 16384 + so, pvh + g * 16);
            cp_async16(base + 24576 + so, pvl + g * 16);
        }
        if (tid < 64) msk[s * 64 + tid] = mask[b * SEQ + kv0 + tid];
    };

    stage_kv(0, 0);
    asm volatile("cp.async.commit_group;");

    for (int jt = 0; jt < SEQ / 64; jt++) {
        if (jt + 1 < SEQ / 64) {
            stage_kv(jt + 1, (jt + 1) & 1);
            asm volatile("cp.async.commit_group;");
            asm volatile("cp.async.wait_group 1;");
        } else {
            asm volatile("cp.async.wait_group 0;");
        }
        __syncthreads();
        const int s = jt & 1;
        const uint32_t Kbase = smb + s * 32768;
        const uint32_t Vbase = Kbase + 16384;
        const int* mskp = msk + s * 64;

        float S[8][4];
#pragma unroll
        for (int i = 0; i < 8; i++)
#pragma unroll
            for (int q = 0; q < 4; q++) S[i][q] = 0.0f;
#pragma unroll
        for (int k16 = 0; k16 < 4; k16++) {
#pragma unroll
            for (int nj = 0; nj < 4; nj++) {
                int row = nj * 16 + ((lane >> 4) << 3) + (lane & 7);
                int g = k16 * 2 + ((lane >> 3) & 1);
                uint32_t so = (uint32_t)(row * 128 + ((g ^ (row & 7)) << 4));
                uint32_t bh0, bh1, bh2, bh3, bl0, bl1, bl2, bl3;
                ldsm4(bh0, bh1, bh2, bh3, Kbase + so);
                ldsm4(bl0, bl1, bl2, bl3, Kbase + 8192 + so);
                mma16816(S[2 * nj], Qh_[k16][0], Qh_[k16][1], Qh_[k16][2], Qh_[k16][3], bh0, bh1);
                mma16816(S[2 * nj], Qh_[k16][0], Qh_[k16][1], Qh_[k16][2], Qh_[k16][3], bl0, bl1);
                mma16816(S[2 * nj], Ql_[k16][0], Ql_[k16][1], Ql_[k16][2], Ql_[k16][3], bh0, bh1);
                mma16816(S[2 * nj + 1], Qh_[k16][0], Qh_[k16][1], Qh_[k16][2], Qh_[k16][3], bh2, bh3);
                mma16816(S[2 * nj + 1], Qh_[k16][0], Qh_[k16][1], Qh_[k16][2], Qh_[k16][3], bl2, bl3);
                mma16816(S[2 * nj + 1], Ql_[k16][0], Ql_[k16][1], Ql_[k16][2], Ql_[k16][3], bh2, bh3);
            }
        }
#pragma unroll
        for (int ni = 0; ni < 8; ni++) {
            int j0 = ni * 8 + lc;
            if (mskp[j0] == 0)     { S[ni][0] = -1e10f; S[ni][2] = -1e10f; }
            if (mskp[j0 + 1] == 0) { S[ni][1] = -1e10f; S[ni][3] = -1e10f; }
        }
        float rmax0 = -1e30f, rmax1 = -1e30f;
#pragma unroll
        for (int ni = 0; ni < 8; ni++) {
            rmax0 = fmaxf(rmax0, fmaxf(S[ni][0], S[ni][1]));
            rmax1 = fmaxf(rmax1, fmaxf(S[ni][2], S[ni][3]));
        }
        rmax0 = fmaxf(rmax0, __shfl_xor_sync(0xffffffffu, rmax0, 1));
        rmax0 = fmaxf(rmax0, __shfl_xor_sync(0xffffffffu, rmax0, 2));
        rmax1 = fmaxf(rmax1, __shfl_xor_sync(0xffffffffu, rmax1, 1));
        rmax1 = fmaxf(rmax1, __shfl_xor_sync(0xffffffffu, rmax1, 2));
        float mn0 = fmaxf(m0r, rmax0), mn1 = fmaxf(m1r, rmax1);
        float corr0 = __expf(m0r - mn0), corr1 = __expf(m1r - mn1);
        m0r = mn0; m1r = mn1;
        float rs0 = 0.0f, rs1 = 0.0f;
#pragma unroll
        for (int ni = 0; ni < 8; ni++) {
            S[ni][0] = __expf(S[ni][0] - mn0); rs0 += S[ni][0];
            S[ni][1] = __expf(S[ni][1] - mn0); rs0 += S[ni][1];
            S[ni][2] = __expf(S[ni][2] - mn1); rs1 += S[ni][2];
            S[ni][3] = __expf(S[ni][3] - mn1); rs1 += S[ni][3];
        }
        rs0 += __shfl_xor_sync(0xffffffffu, rs0, 1);
        rs0 += __shfl_xor_sync(0xffffffffu, rs0, 2);
        rs1 += __shfl_xor_sync(0xffffffffu, rs1, 1);
        rs1 += __shfl_xor_sync(0xffffffffu, rs1, 2);
        l0 = l0 * corr0 + rs0;
        l1 = l1 * corr1 + rs1;
#pragma unroll
        for (int ni = 0; ni < 8; ni++) {
            Of[ni][0] *= corr0; Of[ni][1] *= corr0;
            Of[ni][2] *= corr1; Of[ni][3] *= corr1;
        }
#pragma unroll
        for (int k16 = 0; k16 < 4; k16++) {
            float2 f0 = make_float2(S[2 * k16][0], S[2 * k16][1]);
            float2 f1 = make_float2(S[2 * k16][2], S[2 * k16][3]);
            float2 f2 = make_float2(S[2 * k16 + 1][0], S[2 * k16 + 1][1]);
            float2 f3 = make_float2(S[2 * k16 + 1][2], S[2 * k16 + 1][3]);
            __nv_bfloat162 h0 = __float22bfloat162_rn(f0);
            __nv_bfloat162 h1 = __float22bfloat162_rn(f1);
            __nv_bfloat162 h2 = __float22bfloat162_rn(f2);
            __nv_bfloat162 h3 = __float22bfloat162_rn(f3);
            __nv_bfloat162 e0 = __float22bfloat162_rn(make_float2(f0.x - __low2float(h0), f0.y - __high2float(h0)));
            __nv_bfloat162 e1 = __float22bfloat162_rn(make_float2(f1.x - __low2float(h1), f1.y - __high2float(h1)));
            __nv_bfloat162 e2 = __float22bfloat162_rn(make_float2(f2.x - __low2float(h2), f2.y - __high2float(h2)));
            __nv_bfloat162 e3 = __float22bfloat162_rn(make_float2(f3.x - __low2float(h3), f3.y - __high2float(h3)));
            uint32_t ah0 = *(uint32_t*)&h0, ah1 = *(uint32_t*)&h1, ah2 = *(uint32_t*)&h2, ah3 = *(uint32_t*)&h3;
            uint32_t al0 = *(uint32_t*)&e0, al1 = *(uint32_t*)&e1, al2 = *(uint32_t*)&e2, al3 = *(uint32_t*)&e3;
            int quad = lane >> 3, lr8 = lane & 7;
            int vrow = k16 * 16 + (quad & 1) * 8 + lr8;
#pragma unroll
            for (int nj = 0; nj < 4; nj++) {
                int g = nj * 2 + (quad >> 1);
                uint32_t so = (uint32_t)(vrow * 128 + ((g ^ (vrow & 7)) << 4));
                uint32_t vh0, vh1, vh2, vh3, vl0, vl1, vl2, vl3;
                ldsm4t(vh0, vh1, vh2, vh3, Vbase + so);
                ldsm4t(vl0, vl1, vl2, vl3, Vbase + 8192 + so);
                mma16816(Of[2 * nj], ah0, ah1, ah2, ah3, vh0, vh1);
                mma16816(Of[2 * nj], ah0, ah1, ah2, ah3, vl0, vl1);
                mma16816(Of[2 * nj], al0, al1, al2, al3, vh0, vh1);
                mma16816(Of[2 * nj + 1], ah0, ah1, ah2, ah3, vh2, vh3);
                mma16816(Of[2 * nj + 1], ah0, ah1, ah2, ah3, vl2, vl3);
                mma16816(Of[2 * nj + 1], al0, al1, al2, al3, vh2, vh3);
            }
        }
        __syncthreads();
    }

    // ---- epilogue: (Of/l) * R  -> bf16 hi/lo split ----
    float inv0 = 1.0f / l0, inv1 = 1.0f / l1;
    int r0 = b * SEQ + q0 + wm + lr;
    int r1 = r0 + 8;
#pragma unroll
    for (int ni = 0; ni < 8; ni++) {
        int col = h * DHEAD + ni * 8 + lc;
        size_t o0 = (size_t)r0 * DMODEL + col;
        size_t o1 = (size_t)r1 * DMODEL + col;
        float2 rv0 = *(const float2*)&rmul[o0];
        float2 rv1 = *(const float2*)&rmul[o1];
        float v0 = Of[ni][0] * inv0 * rv0.x;
        float v1 = Of[ni][1] * inv0 * rv0.y;
        float v2 = Of[ni][2] * inv1 * rv1.x;
        float v3 = Of[ni][3] * inv1 * rv1.y;
        __nv_bfloat16 hv[4], lv[4];
        split_store(v0, &hv[0], &lv[0]);
        split_store(v1, &hv[1], &lv[1]);
        split_store(v2, &hv[2], &lv[2]);
        split_store(v3, &hv[3], &lv[3]);
        *(uint32_t*)&oh[o0] = *(uint32_t*)&hv[0];
        *(uint32_t*)&oh[o1] = *(uint32_t*)&hv[2];
        *(uint32_t*)&ol[o0] = *(uint32_t*)&lv[0];
        *(uint32_t*)&ol[o1] = *(uint32_t*)&lv[2];
    }
}

// ---------------- LN2 + KAN + split fused ----------------
__device__ __forceinline__ float2 bspline01(float x) {
    const float h = 2.0f / 7.0f;
    const float i1 = 3.5f;
    const float i2 = 1.75f;
    const float i3 = 7.0f / 6.0f;
    float B0[5];
#pragma unroll
    for (int kk = 0; kk < 5; kk++) {
        float tk = -1.0f + kk * h;
        B0[kk] = (x >= tk && x < tk + h) ? 1.0f : 0.0f;
    }
    float B1[4];
#pragma unroll
    for (int kk = 0; kk < 4; kk++) {
        float tk = -1.0f + kk * h;
        B1[kk] = (x - tk) * i1 * B0[kk] + ((tk + 2.0f * h) - x) * i1 * B0[kk + 1];
    }
    float B2[3];
#pragma unroll
    for (int kk = 0; kk < 3; kk++) {
        float tk = -1.0f + kk * h;
        B2[kk] = (x - tk) * i2 * B1[kk] + ((tk + 3.0f * h) - x) * i2 * B1[kk + 1];
    }
    float2 r;
    {
        float tk = -1.0f;
        r.x = (x - tk) * i3 * B2[0] + ((tk + 4.0f * h) - x) * i3 * B2[1];
        tk = -1.0f + h;
        r.y = (x - tk) * i3 * B2[1] + ((tk + 4.0f * h) - x) * i3 * B2[2];
    }
    return r;
}

__global__ void ln2_kan_split(const float* __restrict__ x,
                              const float* __restrict__ w, const float* __restrict__ b,
                              const float* __restrict__ ic,
                              __nv_bfloat16* __restrict__ hi,
                              __nv_bfloat16* __restrict__ lo) {
    int row = blockIdx.x, t = threadIdx.x;
    float4 o = ln_row(x, w, b, row, t);
    int d0 = t * 4;
    float zz[4] = {o.x, o.y, o.z, o.w};
    __nv_bfloat16 hv[4], lv[4];
#pragma unroll
    for (int q = 0; q < 4; q++) {
        float xv = tanhf(zz[q]);
        float2 bs = bspline01(xv);
        int d = d0 + q;
        float val = bs.x * ic[d * 5 + 0] + bs.y * ic[d * 5 + 1];
        split_store(val, &hv[q], &lv[q]);
    }
    int i = row * (DMODEL / 4) + t;
    ((uint64_t*)hi)[i] = *(uint64_t*)hv;
    ((uint64_t*)lo)[i] = *(uint64_t*)lv;
}

// ---------------- host ----------------
extern "C" void kernel_launch(void* const* d_in, const int* in_sizes, int n_in,
                              void* d_out, int out_size) {
    const float* src    = (const float*)d_in[0];
    const float* ln1_w  = (const float*)d_in[1];
    const float* ln1_b  = (const float*)d_in[2];
    const float* ln2_w  = (const float*)d_in[3];
    const float* ln2_b  = (const float*)d_in[4];
    const float* ln3_w  = (const float*)d_in[5];
    const float* ln3_b  = (const float*)d_in[6];
    const float* Wq_w   = (const float*)d_in[7];
    const float* Wq_b   = (const float*)d_in[8];
    const float* Wk_w   = (const float*)d_in[9];
    const float* Wk_b   = (const float*)d_in[10];
    const float* Wv_w   = (const float*)d_in[11];
    const float* Wv_b   = (const float*)d_in[12];
    const float* Wr_w   = (const float*)d_in[13];
    const float* Wr_b   = (const float*)d_in[14];
    const float* Wo_w   = (const float*)d_in[15];
    const float* Wo_b   = (const float*)d_in[16];
    const float* inner_c= (const float*)d_in[17];
    const float* outer_c= (const float*)d_in[18];
    const int*   mask   = (const int*)d_in[19];
    float* out = (float*)d_out;

    float *r;
    __nv_bfloat16 *wh, *wl, *ah, *al, *qh, *ql, *kh, *kl, *vh, *vl;
    cudaGetSymbolAddress((void**)&r, g_r);
    cudaGetSymbolAddress((void**)&wh, g_wh);
    cudaGetSymbolAddress((void**)&wl, g_wl);
    cudaGetSymbolAddress((void**)&ah, g_ah);
    cudaGetSymbolAddress((void**)&al, g_al);
    cudaGetSymbolAddress((void**)&qh, g_qh);
    cudaGetSymbolAddress((void**)&ql, g_ql);
    cudaGetSymbolAddress((void**)&kh, g_kh);
    cudaGetSymbolAddress((void**)&kl, g_kl);
    cudaGetSymbolAddress((void**)&vh, g_vh);
    cudaGetSymbolAddress((void**)&vl, g_vl);

    cudaFuncSetAttribute(attn_mma, cudaFuncAttributeMaxDynamicSharedMemorySize, AT_SMEM);
    cudaFuncSetAttribute(qkvr_gemm, cudaFuncAttributeMaxDynamicSharedMemorySize, GEMM_SMEM);
    cudaFuncSetAttribute(mma_gemm<true, true>, cudaFuncAttributeMaxDynamicSharedMemorySize, GEMM_SMEM);
    cudaFuncSetAttribute(mma_gemm<false, true>, cudaFuncAttributeMaxDynamicSharedMemorySize, GEMM_SMEM);

    // weights -> fused bf16 hi/lo, one launch
    {
        int n4 = 24 * MAT / 4;
        weight_prep<<<(n4 + 255) / 256, 256>>>(Wq_w, Wk_w, Wv_w, Wr_w, Wo_w, outer_c, wh, wl);
    }

    cudaMemcpyAsync(out, src, (size_t)ROWS * DMODEL * sizeof(float),
                    cudaMemcpyDeviceToDevice, 0);

    dim3 ggrid(DMODEL / 128, ROWS / 128);
    dim3 qgrid(2048 / 128, ROWS / 128);

    // ln1 for layer 0
    ln_split_kernel<<<ROWS, 128>>>(out, ln1_w, ln1_b, ah, al);

    for (int l = 0; l < NLAYER; l++) {
        const __nv_bfloat16* whQ = wh + (size_t)(4 * l) * MAT;
        const __nv_bfloat16* wlQ = wl + (size_t)(4 * l) * MAT;
        const __nv_bfloat16* whO = wh + (size_t)(16 + l) * MAT;
        const __nv_bfloat16* wlO = wl + (size_t)(16 + l) * MAT;
        const __nv_bfloat16* whC = wh + (size_t)(20 + l) * MAT;
        const __nv_bfloat16* wlC = wl + (size_t)(20 + l) * MAT;
        // --- attention block ---
        qkvr_gemm<<<qgrid, 256, GEMM_SMEM>>>(ah, al, whQ, wlQ,
                                             Wq_b + l * DMODEL, Wk_b + l * DMODEL,
                                             Wv_b + l * DMODEL, Wr_b + l * DMODEL,
                                             qh, ql, kh, kl, vh, vl, r);
        attn_mma<<<dim3(SEQ / 128, NHEAD, BSZ), 256, AT_SMEM>>>(qh, ql, kh, kl, vh, vl,
                                                                mask, r, ah, al);
        mma_gemm<true, true><<<ggrid, 256, GEMM_SMEM>>>(ah, al, whO, wlO, Wo_b + l * DMODEL, out, out);
        // --- KAN block ---
        ln2_kan_split<<<ROWS, 128>>>(out, ln2_w + l * DMODEL, ln2_b + l * DMODEL,
                                     inner_c + l * DMODEL * 5, ah, al);
        mma_gemm<false, true><<<ggrid, 256, GEMM_SMEM>>>(ah, al, whC, wlC, nullptr, out, out);
        // --- LN3 (+ next layer LN1 + split) ---
        if (l < NLAYER - 1) {
            ln3_ln1_kernel<<<ROWS, 128>>>(out, ln3_w + l * DMODEL, ln3_b + l * DMODEL,
                                          ln1_w + (l + 1) * DMODEL, ln1_b + (l + 1) * DMODEL,
                                          out, ah, al);
        } else {
            ln_kernel<<<ROWS, 128>>>(out, ln3_w + l * DMODEL, ln3_b + l * DMODEL, out);
        }
    }
}